// round 11
// baseline (speedup 1.0000x reference)
#include <cuda_runtime.h>
#include <cuda_bf16.h>
#include <math.h>
#include <stdint.h>

#define MROWS 4096          // B*S
#define DM    1024          // D_MODEL = INNER

// ---------------- scratch ----------------
__device__ float g_vs[MROWS*DM];
__device__ float g_vc[MROWS*DM];

__device__ __nv_bfloat16 g_xh[MROWS*DM];
__device__ __nv_bfloat16 g_xl[MROWS*DM];
__device__ __nv_bfloat16 g_wth[7*DM*DM];   // transposed weights [n][k], hi
__device__ __nv_bfloat16 g_wtl[7*DM*DM];   // lo
__device__ __nv_bfloat16 g_ath[MROWS*DM];
__device__ __nv_bfloat16 g_atl[MROWS*DM];

// roped + split q/k (hi/lo)
__device__ __nv_bfloat16 g_qsh[MROWS*DM];
__device__ __nv_bfloat16 g_qsl[MROWS*DM];
__device__ __nv_bfloat16 g_ksh[MROWS*DM];
__device__ __nv_bfloat16 g_ksl[MROWS*DM];
__device__ __nv_bfloat16 g_qch[MROWS*DM];
__device__ __nv_bfloat16 g_qcl[MROWS*DM];
__device__ __nv_bfloat16 g_kch[MROWS*DM];
__device__ __nv_bfloat16 g_kcl[MROWS*DM];
// V transposed: [(b*1024 + h*64 + d)][512 s]
__device__ __nv_bfloat16 g_vsth[MROWS*DM];
__device__ __nv_bfloat16 g_vstl[MROWS*DM];
__device__ __nv_bfloat16 g_vcth[MROWS*DM];
__device__ __nv_bfloat16 g_vctl[MROWS*DM];

__device__ float g_cos[512*32];
__device__ float g_sin[512*32];

// ---------------- helpers ----------------
__device__ __forceinline__ uint32_t smem_u32(const void* p) {
    uint32_t a;
    asm("{ .reg .u64 t; cvta.to.shared.u64 t, %1; cvt.u32.u64 %0, t; }" : "=r"(a) : "l"(p));
    return a;
}
#define CP16(dst, src)    asm volatile("cp.async.cg.shared.global [%0], [%1], 16;" :: "r"(dst), "l"(src) : "memory")
#define CP_COMMIT()       asm volatile("cp.async.commit_group;" ::: "memory")
#define CP_WAIT(n)        asm volatile("cp.async.wait_group %0;" :: "n"(n) : "memory")

__device__ __forceinline__ uint32_t ld32s(uint32_t a) {
    uint32_t v;
    asm volatile("ld.shared.b32 %0, [%1];" : "=r"(v) : "r"(a));
    return v;
}
__device__ __forceinline__ float ldf32s(uint32_t a) {
    float v;
    asm volatile("ld.shared.f32 %0, [%1];" : "=f"(v) : "r"(a));
    return v;
}
__device__ __forceinline__ void mma16816(float* c, const uint32_t* a, uint32_t b0, uint32_t b1) {
    asm volatile("mma.sync.aligned.m16n8k16.row.col.f32.bf16.bf16.f32 "
        "{%0,%1,%2,%3}, {%4,%5,%6,%7}, {%8,%9}, {%0,%1,%2,%3};"
        : "+f"(c[0]), "+f"(c[1]), "+f"(c[2]), "+f"(c[3])
        : "r"(a[0]), "r"(a[1]), "r"(a[2]), "r"(a[3]), "r"(b0), "r"(b1));
}
__device__ __forceinline__ uint32_t pack_bf2(float a, float b) {
    __nv_bfloat162 t;
    t.x = __float2bfloat16(a); t.y = __float2bfloat16(b);
    return *(uint32_t*)&t;
}
// split pair (a,b) -> hi u32, lo u32 (residual)
__device__ __forceinline__ void split2(float a, float b, uint32_t& hi, uint32_t& lo) {
    hi = pack_bf2(a, b);
    __nv_bfloat162* t = (__nv_bfloat162*)&hi;
    lo = pack_bf2(a - __bfloat162float(t->x), b - __bfloat162float(t->y));
}

// ---------------- merged prep: x split + weight transpose/split + rope table ----------------
struct W7 { const float* w[7]; };

__global__ __launch_bounds__(256) void prep_all(const float* __restrict__ x, W7 ws)
{
    __shared__ float tile[32][33];
    const int bx = blockIdx.x, tid = threadIdx.x;

    if (bx < 4096) {
        // ---- convert_split of x ----
        int i = bx * 256 + tid;
        float4 v = *(const float4*)(x + (size_t)i * 4);
        uint32_t h0, l0, h1, l1;
        split2(v.x, v.y, h0, l0);
        split2(v.z, v.w, h1, l1);
        uint2 hp = {h0, h1}, lp = {l0, l1};
        *(uint2*)((uint16_t*)g_xh + (size_t)i * 4) = hp;
        *(uint2*)((uint16_t*)g_xl + (size_t)i * 4) = lp;
    } else if (bx < 4096 + 7168) {
        // ---- weight transpose + split ----
        int rem = bx - 4096;
        int bz = rem >> 10;            // 0..6
        rem &= 1023;
        int n0 = (rem & 31) * 32, k0 = (rem >> 5) * 32;
        int tx = tid & 31, ty = tid >> 5;
        const float* W = ws.w[bz];
        __nv_bfloat16* oh = g_wth + (size_t)bz * DM * DM;
        __nv_bfloat16* ol = g_wtl + (size_t)bz * DM * DM;
        #pragma unroll
        for (int j = 0; j < 4; j++)
            tile[ty + j*8][tx] = W[(size_t)(k0 + ty + j*8) * DM + n0 + tx];
        __syncthreads();
        #pragma unroll
        for (int j = 0; j < 4; j++) {
            float v = tile[tx][ty + j*8];
            __nv_bfloat16 h = __float2bfloat16(v);
            __nv_bfloat16 l = __float2bfloat16(v - __bfloat162float(h));
            size_t o = (size_t)(n0 + ty + j*8) * DM + k0 + tx;
            oh[o] = h; ol[o] = l;
        }
    } else {
        // ---- rope table ----
        int p = (bx - 11264) * 256 + tid;   // 16384 entries
        int i = p & 31, s = p >> 5;
        float inv_freq = powf(10000.0f, -((float)(2*i)) * (1.0f/64.0f));
        float f = (float)s * inv_freq;
        double sd, cd; sincos((double)f, &sd, &cd);
        g_cos[p] = (float)cd; g_sin[p] = (float)sd;
    }
}

// ---------------- V transpose + split (unchanged) ----------------
__global__ __launch_bounds__(256) void vtrans()
{
    __shared__ float t[32][33];
    int tx = threadIdx.x & 31, ty = threadIdx.x >> 5;
    int c0 = blockIdx.x * 32, s0 = blockIdx.y * 32;
    int b = blockIdx.z >> 1, w = blockIdx.z & 1;
    const float* src = w ? g_vc : g_vs;
    __nv_bfloat16* oh = w ? g_vcth : g_vsth;
    __nv_bfloat16* ol = w ? g_vctl : g_vstl;
    #pragma unroll
    for (int j = 0; j < 4; j++)
        t[ty + j*8][tx] = src[(size_t)(b*512 + s0 + ty + j*8) * DM + c0 + tx];
    __syncthreads();
    #pragma unroll
    for (int j = 0; j < 4; j++) {
        float v = t[tx][ty + j*8];
        __nv_bfloat16 h = __float2bfloat16(v);
        __nv_bfloat16 l = __float2bfloat16(v - __bfloat162float(h));
        size_t o = (size_t)(b*1024 + c0 + ty + j*8) * 512 + s0 + tx;
        oh[o] = h; ol[o] = l;
    }
}

// ---------------- mma.sync split-bf16 GEMM v6 ----------------
// Mainloop identical to R9 (empirical optimum). NEW: fused epilogue modes:
//   0: fp32 store        (v_s, v_c, final out-proj)
//   1: bf16 hi/lo split  (q_c, k_c)
//   2: rope + split      (q_s, k_s) via smem staging (stage buffers reused)
#define ROWB  112
#define BUFB  (128*ROWB)             // 14336
#define STGB  (4*BUFB)               // 57344
#define GEMM_SMEM (2*STGB)           // 114688 -> 2 CTAs/SM

struct TCGemm {
    const __nv_bfloat16 *Ah, *Al, *Bh, *Bl;
    float*         Cf[6];
    __nv_bfloat16* Ch[6];
    __nv_bfloat16* Cl[6];
    int mode[6];
};

__global__ __launch_bounds__(256) void mma_gemm(TCGemm g)
{
    extern __shared__ char smem[];
    const uint32_t sb = smem_u32(smem);

    const int tid = threadIdx.x, wid = tid >> 5, lane = tid & 31;
    const int n0 = blockIdx.x * 128, m0 = blockIdx.y * 128, z = blockIdx.z;
    const int wm = wid & 1, wn = wid >> 1;
    const int gg = lane >> 2, tt = lane & 3;

    const __nv_bfloat16* bps[4];
    bps[0] = g.Ah + (size_t)m0 * DM;
    bps[1] = g.Al + (size_t)m0 * DM;
    bps[2] = g.Bh + (size_t)z * DM * DM + (size_t)n0 * DM;
    bps[3] = g.Bl + (size_t)z * DM * DM + (size_t)n0 * DM;

    auto load_stage = [&](int s, int kc) {
        uint32_t base = sb + s * STGB;
        #pragma unroll
        for (int buf = 0; buf < 4; buf++) {
            const __nv_bfloat16* bp = bps[buf] + kc * 32;
            #pragma unroll
            for (int it = 0; it < 2; it++) {
                int idx = it * 256 + tid;
                int r = idx >> 2, c = idx & 3;
                CP16(base + buf * BUFB + r * ROWB + c * 16, bp + (size_t)r * DM + c * 8);
            }
        }
        CP_COMMIT();
    };

    float acc[4][4][4];
    #pragma unroll
    for (int i = 0; i < 4; i++)
        #pragma unroll
        for (int j = 0; j < 4; j++)
            #pragma unroll
            for (int k = 0; k < 4; k++) acc[i][j][k] = 0.f;

    load_stage(0, 0);

    for (int s = 0; s < 32; s++) {
        if (s + 1 < 32) { load_stage((s + 1) & 1, s + 1); CP_WAIT(1); }
        else            { CP_WAIT(0); }
        __syncthreads();

        const uint32_t stg = sb + (s & 1) * STGB;
        const uint32_t ahB = stg, alB = stg + BUFB, bhB = stg + 2*BUFB, blB = bhB + BUFB;

        #pragma unroll
        for (int kk = 0; kk < 2; kk++) {
            const uint32_t kOff = (kk * 16 + 2 * tt) * 2;

            uint32_t a_h[4][4], a_l[4][4];
            #pragma unroll
            for (int mf = 0; mf < 4; mf++) {
                uint32_t o0 = (wm*64 + mf*16 + gg) * ROWB + kOff;
                a_h[mf][0] = ld32s(ahB + o0);
                a_h[mf][1] = ld32s(ahB + o0 + 8*ROWB);
                a_h[mf][2] = ld32s(ahB + o0 + 16);
                a_h[mf][3] = ld32s(ahB + o0 + 8*ROWB + 16);
                a_l[mf][0] = ld32s(alB + o0);
                a_l[mf][1] = ld32s(alB + o0 + 8*ROWB);
                a_l[mf][2] = ld32s(alB + o0 + 16);
                a_l[mf][3] = ld32s(alB + o0 + 8*ROWB + 16);
            }
            uint32_t bh0[4], bh1[4], bl0[4], bl1[4];
            #pragma unroll
            for (int nf = 0; nf < 4; nf++) {
                uint32_t o = (wn*32 + nf*8 + gg) * ROWB + kOff;
                bh0[nf] = ld32s(bhB + o); bh1[nf] = ld32s(bhB + o + 16);
                bl0[nf] = ld32s(blB + o); bl1[nf] = ld32s(blB + o + 16);
            }

            #pragma unroll
            for (int mf = 0; mf < 4; mf++)
                #pragma unroll
                for (int nf = 0; nf < 4; nf++)
                    mma16816(acc[mf][nf], a_h[mf], bh0[nf], bh1[nf]);
            #pragma unroll
            for (int mf = 0; mf < 4; mf++)
                #pragma unroll
                for (int nf = 0; nf < 4; nf++)
                    mma16816(acc[mf][nf], a_h[mf], bl0[nf], bl1[nf]);
            #pragma unroll
            for (int mf = 0; mf < 4; mf++)
                #pragma unroll
                for (int nf = 0; nf < 4; nf++)
                    mma16816(acc[mf][nf], a_l[mf], bh0[nf], bh1[nf]);
        }
        __syncthreads();
    }

    // ---------------- fused epilogue ----------------
    const int mode = g.mode[z];

    if (mode == 0) {
        float* C = g.Cf[z];
        #pragma unroll
        for (int mf = 0; mf < 4; mf++) {
            int row0 = m0 + wm*64 + mf*16 + gg;
            #pragma unroll
            for (int nf = 0; nf < 4; nf++) {
                int col = n0 + wn*32 + nf*8 + 2*tt;
                *(float2*)(C + (size_t)row0 * DM + col)       = make_float2(acc[mf][nf][0], acc[mf][nf][1]);
                *(float2*)(C + (size_t)(row0 + 8) * DM + col) = make_float2(acc[mf][nf][2], acc[mf][nf][3]);
            }
        }
    } else if (mode == 1) {
        // direct split from registers (q_c / k_c)
        __nv_bfloat16* Ch = g.Ch[z];
        __nv_bfloat16* Cl = g.Cl[z];
        #pragma unroll
        for (int mf = 0; mf < 4; mf++) {
            int row0 = m0 + wm*64 + mf*16 + gg;
            #pragma unroll
            for (int nf = 0; nf < 4; nf++) {
                int col = n0 + wn*32 + nf*8 + 2*tt;
                uint32_t h0, l0, h1, l1;
                split2(acc[mf][nf][0], acc[mf][nf][1], h0, l0);
                split2(acc[mf][nf][2], acc[mf][nf][3], h1, l1);
                *(uint32_t*)(Ch + (size_t)row0 * DM + col)       = h0;
                *(uint32_t*)(Cl + (size_t)row0 * DM + col)       = l0;
                *(uint32_t*)(Ch + (size_t)(row0 + 8) * DM + col) = h1;
                *(uint32_t*)(Cl + (size_t)(row0 + 8) * DM + col) = l1;
            }
        }
    } else {
        // rope + split (q_s / k_s): stage fp32 tile in smem (stride 130 floats)
        float* sst = (float*)smem;
        #pragma unroll
        for (int mf = 0; mf < 4; mf++) {
            int r0 = wm*64 + mf*16 + gg;
            #pragma unroll
            for (int nf = 0; nf < 4; nf++) {
                int col = wn*32 + nf*8 + 2*tt;
                *(float2*)(sst + (size_t)r0 * 130 + col)       = make_float2(acc[mf][nf][0], acc[mf][nf][1]);
                *(float2*)(sst + (size_t)(r0 + 8) * 130 + col) = make_float2(acc[mf][nf][2], acc[mf][nf][3]);
            }
        }
        __syncthreads();

        __nv_bfloat16* Ch = g.Ch[z];
        __nv_bfloat16* Cl = g.Cl[z];
        const int r  = tid >> 1;           // 0..127
        const int hh = tid & 1;            // head-half within 128-col tile
        const int s  = (m0 + r) & 511;
        const float* srow = sst + (size_t)r * 130 + hh * 64;
        const size_t gbase = (size_t)(m0 + r) * DM + n0 + hh * 64;
        #pragma unroll
        for (int c = 0; c < 32; c += 2) {
            float f0 = srow[c],      f1 = srow[c + 1];
            float q0 = srow[c + 32], q1 = srow[c + 33];
            float c0v = g_cos[s*32 + c], c1v = g_cos[s*32 + c + 1];
            float s0v = g_sin[s*32 + c], s1v = g_sin[s*32 + c + 1];
            float lo0 = f0 * c0v - q0 * s0v;
            float lo1 = f1 * c1v - q1 * s1v;
            float hi0 = q0 * c0v + f0 * s0v;
            float hi1 = q1 * c1v + f1 * s1v;
            uint32_t hA, lA, hB, lB;
            split2(lo0, lo1, hA, lA);
            split2(hi0, hi1, hB, lB);
            *(uint32_t*)(Ch + gbase + c)      = hA;
            *(uint32_t*)(Cl + gbase + c)      = lA;
            *(uint32_t*)(Ch + gbase + c + 32) = hB;
            *(uint32_t*)(Cl + gbase + c + 32) = lB;
        }
    }
}

// ---------------- mma.sync chain-aware flash attention (unchanged, validated) ----------------
#define TSTR   144
#define AQ_B   (128*TSTR)
#define AK_B   (64*TSTR)
#define KVSTG  (8*AK_B)
#define CK_O   (4*AQ_B + 2*KVSTG)
#define AT_SMEM (CK_O + 1024)

struct AttnP {
    const __nv_bfloat16 *q0, *q1, *q2, *q3;
    const __nv_bfloat16 *k0, *k1, *k2, *k3;
    const __nv_bfloat16 *v0, *v1, *v2, *v3;
    const int* chain;
    const int* amask;
};

__global__ __launch_bounds__(256, 1) void attn_mma(AttnP P)
{
    extern __shared__ char smem[];
    const uint32_t sb = smem_u32(smem);

    const int tid = threadIdx.x, wid = tid >> 5, lane = tid & 31;
    const int gg = lane >> 2, tt = lane & 3;
    const int qt = blockIdx.x, h = blockIdx.y, b = blockIdx.z;
    const int q0 = qt * 128;
    const int wq = wid * 16;

    auto ldQ = [&](const __nv_bfloat16* gp, uint32_t so) {
        #pragma unroll
        for (int it = 0; it < 4; it++) {
            int idx = it * 256 + tid, r = idx >> 3, c = idx & 7;
            CP16(sb + so + r*TSTR + c*16,
                 gp + (size_t)(b*512 + q0 + r) * DM + h*64 + c*8);
        }
    };
    ldQ(P.q0, 0); ldQ(P.q1, AQ_B); ldQ(P.q2, 2*AQ_B); ldQ(P.q3, 3*AQ_B);

    auto load_kv = [&](int kt) {
        const int s = kt & 1;
        const uint32_t base = sb + 4*AQ_B + s*KVSTG;
        const int k0g = kt * 64;
        auto ldK = [&](const __nv_bfloat16* gp, uint32_t so) {
            #pragma unroll
            for (int it = 0; it < 2; it++) {
                int idx = it * 256 + tid, r = idx >> 3, c = idx & 7;
                CP16(base + so + r*TSTR + c*16,
                     gp + (size_t)(b*512 + k0g + r) * DM + h*64 + c*8);
            }
        };
        auto ldV = [&](const __nv_bfloat16* gp, uint32_t so) {
            #pragma unroll
            for (int it = 0; it < 2; it++) {
                int idx = it * 256 + tid, r = idx >> 3, c = idx & 7;
                CP16(base + so + r*TSTR + c*16,
                     gp + (size_t)(b*1024 + h*64 + r) * 512 + k0g + c*8);
            }
        };
        ldK(P.k0, 0);      ldK(P.k1, AK_B);   ldK(P.k2, 2*AK_B); ldK(P.k3, 3*AK_B);
        ldV(P.v0, 4*AK_B); ldV(P.v1, 5*AK_B); ldV(P.v2, 6*AK_B); ldV(P.v3, 7*AK_B);
        if (tid < 64) {
            int ck = P.chain[b*512 + k0g + tid];
            float pv = (P.amask[b*512 + k0g + tid] != 0) ? 0.0f : -1e30f;
            ((int*)  (smem))[ (CK_O + s*256)/4 + tid ] = ck;
            ((float*)(smem))[ (CK_O + 512 + s*256)/4 + tid ] = pv;
        }
        CP_COMMIT();
    };

    const int sA = q0 + wq + gg;
    const int cqA = P.chain[b*512 + sA];
    const int cqB = P.chain[b*512 + sA + 8];

    float m0 = -1e30f, m1 = -1e30f, l0 = 0.f, l1 = 0.f;
    float o[8][4];
    #pragma unroll
    for (int n = 0; n < 8; n++)
        #pragma unroll
        for (int c = 0; c < 4; c++) o[n][c] = 0.f;

    load_kv(0);

    for (int kt = 0; kt < 8; kt++) {
        if (kt + 1 < 8) { load_kv(kt + 1); CP_WAIT(1); }
        else            { CP_WAIT(0); }
        __syncthreads();

        const uint32_t kb = sb + 4*AQ_B + (kt & 1)*KVSTG;
        const uint32_t ckb  = sb + CK_O + (kt & 1)*256;
        const uint32_t padb = sb + CK_O + 512 + (kt & 1)*256;

        float ss[8][4], sc[8][4];
        #pragma unroll
        for (int n = 0; n < 8; n++)
            #pragma unroll
            for (int c = 0; c < 4; c++) { ss[n][c] = 0.f; sc[n][c] = 0.f; }

        #pragma unroll
        for (int j = 0; j < 4; j++) {
            const uint32_t ao = (wq + gg)*TSTR + j*32 + tt*4;
            uint32_t qsh[4], qsl[4], qch[4], qcl[4];
            qsh[0] = ld32s(sb + ao);            qsh[1] = ld32s(sb + ao + 8*TSTR);
            qsh[2] = ld32s(sb + ao + 16);       qsh[3] = ld32s(sb + ao + 8*TSTR + 16);
            qsl[0] = ld32s(sb + AQ_B + ao);     qsl[1] = ld32s(sb + AQ_B + ao + 8*TSTR);
            qsl[2] = ld32s(sb + AQ_B + ao + 16);qsl[3] = ld32s(sb + AQ_B + ao + 8*TSTR + 16);
            qch[0] = ld32s(sb + 2*AQ_B + ao);            qch[1] = ld32s(sb + 2*AQ_B + ao + 8*TSTR);
            qch[2] = ld32s(sb + 2*AQ_B + ao + 16);       qch[3] = ld32s(sb + 2*AQ_B + ao + 8*TSTR + 16);
            qcl[0] = ld32s(sb + 3*AQ_B + ao);            qcl[1] = ld32s(sb + 3*AQ_B + ao + 8*TSTR);
            qcl[2] = ld32s(sb + 3*AQ_B + ao + 16);       qcl[3] = ld32s(sb + 3*AQ_B + ao + 8*TSTR + 16);

            #pragma unroll
            for (int n = 0; n < 8; n++) {
                const uint32_t bo = (n*8 + gg)*TSTR + j*32 + tt*4;
                uint32_t ksh0 = ld32s(kb + bo),          ksh1 = ld32s(kb + bo + 16);
                uint32_t ksl0 = ld32s(kb + AK_B + bo),   ksl1 = ld32s(kb + AK_B + bo + 16);
                uint32_t kch0 = ld32s(kb + 2*AK_B + bo), kch1 = ld32s(kb + 2*AK_B + bo + 16);
                uint32_t kcl0 = ld32s(kb + 3*AK_B + bo), kcl1 = ld32s(kb + 3*AK_B + bo + 16);
                mma16816(ss[n], qsh, ksh0, ksh1);
                mma16816(ss[n], qsh, ksl0, ksl1);
                mma16816(ss[n], qsl, ksh0, ksh1);
                mma16816(sc[n], qch, kch0, kch1);
                mma16816(sc[n], qch, kcl0, kcl1);
                mma16816(sc[n], qcl, kch0, kch1);
            }
        }

        int   ckE[8], ckO[8];
        float pdE[8], pdO[8];
        #pragma unroll
        for (int n = 0; n < 8; n++) {
            ckE[n] = (int)ld32s(ckb + (n*8 + 2*tt)*4);
            ckO[n] = (int)ld32s(ckb + (n*8 + 2*tt + 1)*4);
            pdE[n] = ldf32s(padb + (n*8 + 2*tt)*4);
            pdO[n] = ldf32s(padb + (n*8 + 2*tt + 1)*4);
        }

        #pragma unroll
        for (int n = 0; n < 8; n++) {
            ss[n][0] = ((ckE[n]==cqA) ? ss[n][0] : sc[n][0]) * 0.125f + pdE[n];
            ss[n][1] = ((ckO[n]==cqA) ? ss[n][1] : sc[n][1]) * 0.125f + pdO[n];
            ss[n][2] = ((ckE[n]==cqB) ? ss[n][2] : sc[n][2]) * 0.125f + pdE[n];
            ss[n][3] = ((ckO[n]==cqB) ? ss[n][3] : sc[n][3]) * 0.125f + pdO[n];
        }

        float r0 = -1e30f, r1 = -1e30f;
        #pragma unroll
        for (int n = 0; n < 8; n++) {
            r0 = fmaxf(r0, fmaxf(ss[n][0], ss[n][1]));
            r1 = fmaxf(r1, fmaxf(ss[n][2], ss[n][3]));
        }
        r0 = fmaxf(r0, __shfl_xor_sync(0xffffffffu, r0, 1));
        r0 = fmaxf(r0, __shfl_xor_sync(0xffffffffu, r0, 2));
        r1 = fmaxf(r1, __shfl_xor_sync(0xffffffffu, r1, 1));
        r1 = fmaxf(r1, __shfl_xor_sync(0xffffffffu, r1, 2));

        float mn0 = fmaxf(m0, r0), mn1 = fmaxf(m1, r1);
        float al0 = __expf(m0 - mn0), al1 = __expf(m1 - mn1);
        m0 = mn0; m1 = mn1;

        float ts0 = 0.f, ts1 = 0.f;
        #pragma unroll
        for (int n = 0; n < 8; n++) {
            float vaE = (pdE[n] == 0.f) ? 1.f : 0.f;
            float vaO = (pdO[n] == 0.f) ? 1.f : 0.f;
            float e0 = __expf(ss[n][0] - mn0) * vaE;
            float e1 = __expf(ss[n][1] - mn0) * vaO;
            float e2 = __expf(ss[n][2] - mn1) * vaE;
            float e3 = __expf(ss[n][3] - mn1) * vaO;
            ts0 += e0 + e1; ts1 += e2 + e3;
            float p0 = (ckE[n]==cqA) ? e0 : 0.f;
            float p1 = (ckO[n]==cqA) ? e1 : 0.f;
            float p2 = (ckE[n]==cqB) ? e2 : 0.f;
            float p3 = (ckO[n]==cqB) ? e3 : 0.f;
            sc[n][0] = e0 - p0; sc[n][1] = e1 - p1; sc[n][2] = e2 - p2; sc[n][3] = e3 - p3;
            ss[n][0] = p0; ss[n][1] = p1; ss[n][2] = p2; ss[n][3] = p3;
        }
        ts0 += __shfl_xor_sync(0xffffffffu, ts0, 1);
        ts0 += __shfl_xor_sync(0xffffffffu, ts0, 2);
        ts1 += __shfl_xor_sync(0xffffffffu, ts1, 1);
        ts1 += __shfl_xor_sync(0xffffffffu, ts1, 2);
        l0 = l0 * al0 + ts0;
        l1 = l1 * al1 + ts1;

        #pragma unroll
        for (int n = 0; n < 8; n++) {
            o[n][0] *= al0; o[n][1] *= al0; o[n][2] *= al1; o[n][3] *= al1;
        }

        #pragma unroll
        for (int j = 0; j < 4; j++) {
            const int n0t = 2*j, n1t = 2*j + 1;
            uint32_t ash[4], asl[4], ach[4], acl[4];
            {
                split2(ss[n0t][0], ss[n0t][1], ash[0], asl[0]);
                split2(ss[n0t][2], ss[n0t][3], ash[1], asl[1]);
                split2(ss[n1t][0], ss[n1t][1], ash[2], asl[2]);
                split2(ss[n1t][2], ss[n1t][3], ash[3], asl[3]);
                split2(sc[n0t][0], sc[n0t][1], ach[0], acl[0]);
                split2(sc[n0t][2], sc[n0t][3], ach[1], acl[1]);
                split2(sc[n1t][0], sc[n1t][1], ach[2], acl[2]);
                split2(sc[n1t][2], sc[n1t][3], ach[3], acl[3]);
            }
            #pragma unroll
            for (int n = 0; n < 8; n++) {
                const uint32_t vo = (n*8 + gg)*TSTR + j*32 + tt*4;
                uint32_t vsh0 = ld32s(kb + 4*AK_B + vo), vsh1 = ld32s(kb + 4*AK_B + vo + 16);
                uint32_t vsl0 = ld32s(kb + 5*AK_B + vo), vsl1 = ld32s(kb + 5*AK_B + vo + 16);
                uint32_t vch0 = ld32s(kb + 6*AK_B + vo), vch1 = ld32s(kb + 6*AK_B + vo + 16);
                uint32_t vcl0 = ld32s(kb + 7*AK_B + vo), vcl1 = ld32s(kb + 7*AK_B + vo + 16);
                mma16816(o[n], ash, vsh0, vsh1);
                mma16816(o[n], ash, vsl0, vsl1);
                mma16816(o[n], asl, vsh0, vsh1);
                mma16816(o[n], ach, vch0, vch1);
                mma16816(o[n], ach, vcl0, vcl1);
                mma16816(o[n], acl, vch0, vch1);
            }
        }
        __syncthreads();
    }

    float li0 = (l0 > 0.f) ? (1.f / l0) : 0.f;
    float li1 = (l1 > 0.f) ? (1.f / l1) : 0.f;
    const size_t rA = (size_t)(b*512 + q0 + wq + gg) * DM + h*64;
    const size_t rB = rA + (size_t)8 * DM;
    #pragma unroll
    for (int n = 0; n < 8; n++) {
        int colg = n*8 + 2*tt;
        float v0 = o[n][0]*li0, v1 = o[n][1]*li0, v2 = o[n][2]*li1, v3 = o[n][3]*li1;
        uint32_t h0, lo0, h1, lo1;
        split2(v0, v1, h0, lo0);
        split2(v2, v3, h1, lo1);
        *(uint32_t*)(g_ath + rA + colg) = h0;
        *(uint32_t*)(g_atl + rA + colg) = lo0;
        *(uint32_t*)(g_ath + rB + colg) = h1;
        *(uint32_t*)(g_atl + rB + colg) = lo1;
    }
}

// ---------------- launch ----------------
extern "C" void kernel_launch(void* const* d_in, const int* in_sizes, int n_in,
                              void* d_out, int out_size)
{
    const float *x, *Wqs, *Wks, *Wvs, *Wqc, *Wkc, *Wvc, *Wo;
    const int *chain, *amask;

    if (in_sizes[0] == MROWS * DM) {
        x     = (const float*)d_in[0];
        chain = (const int*)d_in[1];
        amask = (const int*)d_in[2];
        Wqs = (const float*)d_in[3]; Wks = (const float*)d_in[4]; Wvs = (const float*)d_in[5];
        Wqc = (const float*)d_in[6]; Wkc = (const float*)d_in[7]; Wvc = (const float*)d_in[8];
        Wo  = (const float*)d_in[9];
    } else {
        Wkc = (const float*)d_in[0]; Wks = (const float*)d_in[1]; Wo  = (const float*)d_in[2];
        Wqc = (const float*)d_in[3]; Wqs = (const float*)d_in[4];
        Wvc = (const float*)d_in[5]; Wvs = (const float*)d_in[6];
        amask = (const int*)d_in[7]; chain = (const int*)d_in[8];
        x     = (const float*)d_in[9];
    }

    float *vs, *vc;
    cudaGetSymbolAddress((void**)&vs, g_vs);
    cudaGetSymbolAddress((void**)&vc, g_vc);
    __nv_bfloat16 *xh, *xl, *wth, *wtl, *ath, *atl;
    __nv_bfloat16 *qsh, *qsl, *ksh, *ksl, *qch, *qcl, *kch, *kcl;
    cudaGetSymbolAddress((void**)&xh,  g_xh);
    cudaGetSymbolAddress((void**)&xl,  g_xl);
    cudaGetSymbolAddress((void**)&wth, g_wth);
    cudaGetSymbolAddress((void**)&wtl, g_wtl);
    cudaGetSymbolAddress((void**)&ath, g_ath);
    cudaGetSymbolAddress((void**)&atl, g_atl);
    cudaGetSymbolAddress((void**)&qsh, g_qsh);
    cudaGetSymbolAddress((void**)&qsl, g_qsl);
    cudaGetSymbolAddress((void**)&ksh, g_ksh);
    cudaGetSymbolAddress((void**)&ksl, g_ksl);
    cudaGetSymbolAddress((void**)&qch, g_qch);
    cudaGetSymbolAddress((void**)&qcl, g_qcl);
    cudaGetSymbolAddress((void**)&kch, g_kch);
    cudaGetSymbolAddress((void**)&kcl, g_kcl);

    AttnP ap;
    ap.q0 = qsh; ap.q1 = qsl; ap.q2 = qch; ap.q3 = qcl;
    ap.k0 = ksh; ap.k1 = ksl; ap.k2 = kch; ap.k3 = kcl;
    {
        void* p;
        cudaGetSymbolAddress(&p, g_vsth); ap.v0 = (const __nv_bfloat16*)p;
        cudaGetSymbolAddress(&p, g_vstl); ap.v1 = (const __nv_bfloat16*)p;
        cudaGetSymbolAddress(&p, g_vcth); ap.v2 = (const __nv_bfloat16*)p;
        cudaGetSymbolAddress(&p, g_vctl); ap.v3 = (const __nv_bfloat16*)p;
    }
    ap.chain = chain; ap.amask = amask;

    // 1) merged prep: x split + weight transpose/split + rope table
    W7 ws; ws.w[0]=Wqs; ws.w[1]=Wks; ws.w[2]=Wvs; ws.w[3]=Wqc; ws.w[4]=Wkc; ws.w[5]=Wvc; ws.w[6]=Wo;
    prep_all<<<4096 + 7168 + 64, 256>>>(x, ws);

    // 2) six projections, fused epilogue (rope+split for q_s/k_s, split for q_c/k_c)
    cudaFuncSetAttribute(mma_gemm, cudaFuncAttributeMaxDynamicSharedMemorySize, GEMM_SMEM);
    TCGemm gp = {};
    gp.Ah = xh; gp.Al = xl; gp.Bh = wth; gp.Bl = wtl;
    gp.mode[0] = 2; gp.Ch[0] = qsh; gp.Cl[0] = qsl;   // q_self: rope + split
    gp.mode[1] = 2; gp.Ch[1] = ksh; gp.Cl[1] = ksl;   // k_self: rope + split
    gp.mode[2] = 0; gp.Cf[2] = vs;                    // v_self: fp32
    gp.mode[3] = 1; gp.Ch[3] = qch; gp.Cl[3] = qcl;   // q_cross: split
    gp.mode[4] = 1; gp.Ch[4] = kch; gp.Cl[4] = kcl;   // k_cross: split
    gp.mode[5] = 0; gp.Cf[5] = vc;                    // v_cross: fp32
    mma_gemm<<<dim3(8, 32, 6), 256, GEMM_SMEM>>>(gp);

    // 3) V transpose/split
    vtrans<<<dim3(32, 16, 16), 256>>>();

    // 4) attention
    cudaFuncSetAttribute(attn_mma, cudaFuncAttributeMaxDynamicSharedMemorySize, AT_SMEM);
    attn_mma<<<dim3(4, 16, 8), 256, AT_SMEM>>>(ap);

    // 5) output projection (fp32 to d_out)
    TCGemm go = {};
    go.Ah = ath; go.Al = atl; go.Bh = wth + (size_t)6*DM*DM; go.Bl = wtl + (size_t)6*DM*DM;
    go.mode[0] = 0; go.Cf[0] = (float*)d_out;
    mma_gemm<<<dim3(8, 32, 1), 256, GEMM_SMEM>>>(go);
}

// round 12
// speedup vs baseline: 1.0454x; 1.0454x over previous
#include <cuda_runtime.h>
#include <cuda_bf16.h>
#include <math.h>
#include <stdint.h>

#define MROWS 4096          // B*S
#define DM    1024          // D_MODEL = INNER

// ---------------- scratch ----------------
__device__ float g_qs[MROWS*DM];
__device__ float g_ks[MROWS*DM];
__device__ float g_vs[MROWS*DM];
__device__ float g_qc[MROWS*DM];
__device__ float g_kc[MROWS*DM];
__device__ float g_vc[MROWS*DM];

__device__ __nv_bfloat16 g_xh[MROWS*DM];
__device__ __nv_bfloat16 g_xl[MROWS*DM];
__device__ __nv_bfloat16 g_wth[7*DM*DM];   // transposed weights [n][k], hi
__device__ __nv_bfloat16 g_wtl[7*DM*DM];   // lo
__device__ __nv_bfloat16 g_ath[MROWS*DM];
__device__ __nv_bfloat16 g_atl[MROWS*DM];

// roped + split q/k (hi/lo)
__device__ __nv_bfloat16 g_qsh[MROWS*DM];
__device__ __nv_bfloat16 g_qsl[MROWS*DM];
__device__ __nv_bfloat16 g_ksh[MROWS*DM];
__device__ __nv_bfloat16 g_ksl[MROWS*DM];
__device__ __nv_bfloat16 g_qch[MROWS*DM];
__device__ __nv_bfloat16 g_qcl[MROWS*DM];
__device__ __nv_bfloat16 g_kch[MROWS*DM];
__device__ __nv_bfloat16 g_kcl[MROWS*DM];
// V transposed: [(b*1024 + h*64 + d)][512 s]
__device__ __nv_bfloat16 g_vsth[MROWS*DM];
__device__ __nv_bfloat16 g_vstl[MROWS*DM];
__device__ __nv_bfloat16 g_vcth[MROWS*DM];
__device__ __nv_bfloat16 g_vctl[MROWS*DM];

__device__ float g_cos[512*32];
__device__ float g_sin[512*32];

// ---------------- helpers ----------------
__device__ __forceinline__ uint32_t smem_u32(const void* p) {
    uint32_t a;
    asm("{ .reg .u64 t; cvta.to.shared.u64 t, %1; cvt.u32.u64 %0, t; }" : "=r"(a) : "l"(p));
    return a;
}
#define CP16(dst, src)    asm volatile("cp.async.cg.shared.global [%0], [%1], 16;" :: "r"(dst), "l"(src) : "memory")
#define CP_COMMIT()       asm volatile("cp.async.commit_group;" ::: "memory")
#define CP_WAIT(n)        asm volatile("cp.async.wait_group %0;" :: "n"(n) : "memory")

__device__ __forceinline__ uint32_t ld32s(uint32_t a) {
    uint32_t v;
    asm volatile("ld.shared.b32 %0, [%1];" : "=r"(v) : "r"(a));
    return v;
}
__device__ __forceinline__ float ldf32s(uint32_t a) {
    float v;
    asm volatile("ld.shared.f32 %0, [%1];" : "=f"(v) : "r"(a));
    return v;
}
__device__ __forceinline__ void mma16816(float* c, const uint32_t* a, uint32_t b0, uint32_t b1) {
    asm volatile("mma.sync.aligned.m16n8k16.row.col.f32.bf16.bf16.f32 "
        "{%0,%1,%2,%3}, {%4,%5,%6,%7}, {%8,%9}, {%0,%1,%2,%3};"
        : "+f"(c[0]), "+f"(c[1]), "+f"(c[2]), "+f"(c[3])
        : "r"(a[0]), "r"(a[1]), "r"(a[2]), "r"(a[3]), "r"(b0), "r"(b1));
}
__device__ __forceinline__ uint32_t pack_bf2(float a, float b) {
    __nv_bfloat162 t;
    t.x = __float2bfloat16(a); t.y = __float2bfloat16(b);
    return *(uint32_t*)&t;
}

// ---------------- merged prep 1: x split + weight transpose/split + rope table ----------------
struct W7 { const float* w[7]; };

__global__ __launch_bounds__(256) void prep_all(const float* __restrict__ x, W7 ws)
{
    __shared__ float tile[32][33];
    const int bx = blockIdx.x, tid = threadIdx.x;

    if (bx < 4096) {
        // ---- convert_split of x ----
        int i = bx * 256 + tid;
        float4 v = *(const float4*)(x + (size_t)i * 4);
        __nv_bfloat16 h0 = __float2bfloat16(v.x), h1 = __float2bfloat16(v.y);
        __nv_bfloat16 h2 = __float2bfloat16(v.z), h3 = __float2bfloat16(v.w);
        __nv_bfloat16 l0 = __float2bfloat16(v.x - __bfloat162float(h0));
        __nv_bfloat16 l1 = __float2bfloat16(v.y - __bfloat162float(h1));
        __nv_bfloat16 l2 = __float2bfloat16(v.z - __bfloat162float(h2));
        __nv_bfloat16 l3 = __float2bfloat16(v.w - __bfloat162float(h3));
        __nv_bfloat162 hA = {h0, h1}, hB = {h2, h3}, lA = {l0, l1}, lB = {l2, l3};
        uint2 hp, lp;
        hp.x = *(uint32_t*)&hA; hp.y = *(uint32_t*)&hB;
        lp.x = *(uint32_t*)&lA; lp.y = *(uint32_t*)&lB;
        *(uint2*)((uint16_t*)g_xh + (size_t)i * 4) = hp;
        *(uint2*)((uint16_t*)g_xl + (size_t)i * 4) = lp;
    } else if (bx < 4096 + 7168) {
        // ---- weight transpose + split ----
        int rem = bx - 4096;
        int bz = rem >> 10;            // 0..6
        rem &= 1023;
        int n0 = (rem & 31) * 32, k0 = (rem >> 5) * 32;
        int tx = tid & 31, ty = tid >> 5;
        const float* W = ws.w[bz];
        __nv_bfloat16* oh = g_wth + (size_t)bz * DM * DM;
        __nv_bfloat16* ol = g_wtl + (size_t)bz * DM * DM;
        #pragma unroll
        for (int j = 0; j < 4; j++)
            tile[ty + j*8][tx] = W[(size_t)(k0 + ty + j*8) * DM + n0 + tx];
        __syncthreads();
        #pragma unroll
        for (int j = 0; j < 4; j++) {
            float v = tile[tx][ty + j*8];
            __nv_bfloat16 h = __float2bfloat16(v);
            __nv_bfloat16 l = __float2bfloat16(v - __bfloat162float(h));
            size_t o = (size_t)(n0 + ty + j*8) * DM + k0 + tx;
            oh[o] = h; ol[o] = l;
        }
    } else {
        // ---- rope table ----
        int p = (bx - 11264) * 256 + tid;   // 16384 entries
        int i = p & 31, s = p >> 5;
        float inv_freq = powf(10000.0f, -((float)(2*i)) * (1.0f/64.0f));
        float f = (float)s * inv_freq;
        double sd, cd; sincos((double)f, &sd, &cd);
        g_cos[p] = (float)cd; g_sin[p] = (float)sd;
    }
}

// ---------------- merged prep 2: rope/split of q,k  +  V transpose/split ----------------
__global__ __launch_bounds__(256) void qv_prep()
{
    __shared__ float t[32][33];
    const int bx = blockIdx.x, tid = threadIdx.x;

    if (bx < 8192) {
        // ---- qk_prep (identical numerics to R5) ----
        int p = bx * 256 + tid;
        int i = p & 31, h = (p >> 5) & 15, row = p >> 9, s = row & 511;
        float c  = g_cos[(s << 5) + i];
        float sn = g_sin[(s << 5) + i];
        int base = row * DM + h * 64 + i;

        float q0 = g_qs[base], q1 = g_qs[base + 32];
        float k0 = g_ks[base], k1 = g_ks[base + 32];
        float qr0 = q0 * c - q1 * sn, qr1 = q1 * c + q0 * sn;
        float kr0 = k0 * c - k1 * sn, kr1 = k1 * c + k0 * sn;
        float qc0 = g_qc[base], qc1 = g_qc[base + 32];
        float kc0 = g_kc[base], kc1 = g_kc[base + 32];

        #define SPLIT_ST(arrh, arrl, idx, v) do { \
            __nv_bfloat16 _h = __float2bfloat16(v); \
            arrh[idx] = _h; arrl[idx] = __float2bfloat16((v) - __bfloat162float(_h)); } while (0)
        SPLIT_ST(g_qsh, g_qsl, base, qr0);      SPLIT_ST(g_qsh, g_qsl, base + 32, qr1);
        SPLIT_ST(g_ksh, g_ksl, base, kr0);      SPLIT_ST(g_ksh, g_ksl, base + 32, kr1);
        SPLIT_ST(g_qch, g_qcl, base, qc0);      SPLIT_ST(g_qch, g_qcl, base + 32, qc1);
        SPLIT_ST(g_kch, g_kcl, base, kc0);      SPLIT_ST(g_kch, g_kcl, base + 32, kc1);
        #undef SPLIT_ST
    } else {
        // ---- vtrans (identical numerics to R5) ----
        int rem = bx - 8192;                 // 0..8191 = 32 x 16 x 16
        int c0 = (rem & 31) * 32;
        int s0 = ((rem >> 5) & 15) * 32;
        int z  = rem >> 9;                   // 0..15
        int b = z >> 1, w = z & 1;
        int tx = tid & 31, ty = tid >> 5;
        const float* src = w ? g_vc : g_vs;
        __nv_bfloat16* oh = w ? g_vcth : g_vsth;
        __nv_bfloat16* ol = w ? g_vctl : g_vstl;
        #pragma unroll
        for (int j = 0; j < 4; j++)
            t[ty + j*8][tx] = src[(size_t)(b*512 + s0 + ty + j*8) * DM + c0 + tx];
        __syncthreads();
        #pragma unroll
        for (int j = 0; j < 4; j++) {
            float v = t[tx][ty + j*8];
            __nv_bfloat16 h = __float2bfloat16(v);
            __nv_bfloat16 l = __float2bfloat16(v - __bfloat162float(h));
            size_t o = (size_t)(b*1024 + c0 + ty + j*8) * 512 + s0 + tx;
            oh[o] = h; ol[o] = l;
        }
    }
}

// ---------------- mma.sync split-bf16 GEMM (EXACT R5, 813.6us validated) ----------------
#define ROWB  112                    // smem row stride bytes (7*16B, conflict-free)
#define BUFB  (128*ROWB)             // 14336
#define STGB  (4*BUFB)               // 57344: Ah, Al, Bh, Bl
#define GEMM_SMEM (2*STGB)           // 114688  -> 2 CTAs/SM

struct TCGemm {
    const __nv_bfloat16 *Ah, *Al, *Bh, *Bl;
    float* C[6];
};

__global__ __launch_bounds__(256) void mma_gemm(TCGemm g)
{
    extern __shared__ char smem[];
    const uint32_t sb = smem_u32(smem);

    const int tid = threadIdx.x, wid = tid >> 5, lane = tid & 31;
    const int n0 = blockIdx.x * 128, m0 = blockIdx.y * 128, z = blockIdx.z;
    const int wm = wid & 1, wn = wid >> 1;          // 2 x 4 warp grid, warp 64x32
    const int gg = lane >> 2, tt = lane & 3;

    const __nv_bfloat16* bps[4];
    bps[0] = g.Ah + (size_t)m0 * DM;
    bps[1] = g.Al + (size_t)m0 * DM;
    bps[2] = g.Bh + (size_t)z * DM * DM + (size_t)n0 * DM;
    bps[3] = g.Bl + (size_t)z * DM * DM + (size_t)n0 * DM;

    auto load_stage = [&](int s, int kc) {
        uint32_t base = sb + s * STGB;
        #pragma unroll
        for (int buf = 0; buf < 4; buf++) {
            const __nv_bfloat16* bp = bps[buf] + kc * 32;
            #pragma unroll
            for (int it = 0; it < 2; it++) {
                int idx = it * 256 + tid;
                int r = idx >> 2, c = idx & 3;
                CP16(base + buf * BUFB + r * ROWB + c * 16, bp + (size_t)r * DM + c * 8);
            }
        }
        CP_COMMIT();
    };

    float acc[4][4][4];
    #pragma unroll
    for (int i = 0; i < 4; i++)
        #pragma unroll
        for (int j = 0; j < 4; j++)
            #pragma unroll
            for (int k = 0; k < 4; k++) acc[i][j][k] = 0.f;

    load_stage(0, 0);

    for (int s = 0; s < 32; s++) {
        if (s + 1 < 32) { load_stage((s + 1) & 1, s + 1); CP_WAIT(1); }
        else            { CP_WAIT(0); }
        __syncthreads();

        const uint32_t stg = sb + (s & 1) * STGB;
        const uint32_t ahB = stg, alB = stg + BUFB, bhB = stg + 2*BUFB, blB = bhB + BUFB;

        #pragma unroll
        for (int kk = 0; kk < 2; kk++) {
            const uint32_t kOff = (kk * 16 + 2 * tt) * 2;

            uint32_t a_h[4][4], a_l[4][4];
            #pragma unroll
            for (int mf = 0; mf < 4; mf++) {
                uint32_t o0 = (wm*64 + mf*16 + gg) * ROWB + kOff;
                a_h[mf][0] = ld32s(ahB + o0);
                a_h[mf][1] = ld32s(ahB + o0 + 8*ROWB);
                a_h[mf][2] = ld32s(ahB + o0 + 16);
                a_h[mf][3] = ld32s(ahB + o0 + 8*ROWB + 16);
                a_l[mf][0] = ld32s(alB + o0);
                a_l[mf][1] = ld32s(alB + o0 + 8*ROWB);
                a_l[mf][2] = ld32s(alB + o0 + 16);
                a_l[mf][3] = ld32s(alB + o0 + 8*ROWB + 16);
            }
            #pragma unroll
            for (int nf = 0; nf < 4; nf++) {
                uint32_t o = (wn*32 + nf*8 + gg) * ROWB + kOff;
                uint32_t bh0 = ld32s(bhB + o), bh1 = ld32s(bhB + o + 16);
                uint32_t bl0 = ld32s(blB + o), bl1 = ld32s(blB + o + 16);
                #pragma unroll
                for (int mf = 0; mf < 4; mf++) {
                    mma16816(acc[mf][nf], a_h[mf], bh0, bh1);
                    mma16816(acc[mf][nf], a_h[mf], bl0, bl1);
                    mma16816(acc[mf][nf], a_l[mf], bh0, bh1);
                }
            }
        }
        __syncthreads();
    }

    float* C = g.C[z];
    #pragma unroll
    for (int mf = 0; mf < 4; mf++) {
        int row0 = m0 + wm*64 + mf*16 + gg;
        #pragma unroll
        for (int nf = 0; nf < 4; nf++) {
            int col = n0 + wn*32 + nf*8 + 2*tt;
            *(float2*)(C + (size_t)row0 * DM + col)       = make_float2(acc[mf][nf][0], acc[mf][nf][1]);
            *(float2*)(C + (size_t)(row0 + 8) * DM + col) = make_float2(acc[mf][nf][2], acc[mf][nf][3]);
        }
    }
}

// ---------------- mma.sync chain-aware flash attention (EXACT R5, validated) ----------------
#define TSTR   144
#define AQ_B   (128*TSTR)
#define AK_B   (64*TSTR)
#define KVSTG  (8*AK_B)
#define CK_O   (4*AQ_B + 2*KVSTG)
#define AT_SMEM (CK_O + 1024)

struct AttnP {
    const __nv_bfloat16 *q0, *q1, *q2, *q3;
    const __nv_bfloat16 *k0, *k1, *k2, *k3;
    const __nv_bfloat16 *v0, *v1, *v2, *v3;
    const int* chain;
    const int* amask;
};

__global__ __launch_bounds__(256, 1) void attn_mma(AttnP P)
{
    extern __shared__ char smem[];
    const uint32_t sb = smem_u32(smem);

    const int tid = threadIdx.x, wid = tid >> 5, lane = tid & 31;
    const int gg = lane >> 2, tt = lane & 3;
    const int qt = blockIdx.x, h = blockIdx.y, b = blockIdx.z;
    const int q0 = qt * 128;
    const int wq = wid * 16;

    auto ldQ = [&](const __nv_bfloat16* gp, uint32_t so) {
        #pragma unroll
        for (int it = 0; it < 4; it++) {
            int idx = it * 256 + tid, r = idx >> 3, c = idx & 7;
            CP16(sb + so + r*TSTR + c*16,
                 gp + (size_t)(b*512 + q0 + r) * DM + h*64 + c*8);
        }
    };
    ldQ(P.q0, 0); ldQ(P.q1, AQ_B); ldQ(P.q2, 2*AQ_B); ldQ(P.q3, 3*AQ_B);

    auto load_kv = [&](int kt) {
        const int s = kt & 1;
        const uint32_t base = sb + 4*AQ_B + s*KVSTG;
        const int k0g = kt * 64;
        auto ldK = [&](const __nv_bfloat16* gp, uint32_t so) {
            #pragma unroll
            for (int it = 0; it < 2; it++) {
                int idx = it * 256 + tid, r = idx >> 3, c = idx & 7;
                CP16(base + so + r*TSTR + c*16,
                     gp + (size_t)(b*512 + k0g + r) * DM + h*64 + c*8);
            }
        };
        auto ldV = [&](const __nv_bfloat16* gp, uint32_t so) {
            #pragma unroll
            for (int it = 0; it < 2; it++) {
                int idx = it * 256 + tid, r = idx >> 3, c = idx & 7;
                CP16(base + so + r*TSTR + c*16,
                     gp + (size_t)(b*1024 + h*64 + r) * 512 + k0g + c*8);
            }
        };
        ldK(P.k0, 0);      ldK(P.k1, AK_B);   ldK(P.k2, 2*AK_B); ldK(P.k3, 3*AK_B);
        ldV(P.v0, 4*AK_B); ldV(P.v1, 5*AK_B); ldV(P.v2, 6*AK_B); ldV(P.v3, 7*AK_B);
        if (tid < 64) {
            int ck = P.chain[b*512 + k0g + tid];
            float pv = (P.amask[b*512 + k0g + tid] != 0) ? 0.0f : -1e30f;
            ((int*)  (smem))[ (CK_O + s*256)/4 + tid ] = ck;
            ((float*)(smem))[ (CK_O + 512 + s*256)/4 + tid ] = pv;
        }
        CP_COMMIT();
    };

    const int sA = q0 + wq + gg;
    const int cqA = P.chain[b*512 + sA];
    const int cqB = P.chain[b*512 + sA + 8];

    float m0 = -1e30f, m1 = -1e30f, l0 = 0.f, l1 = 0.f;
    float o[8][4];
    #pragma unroll
    for (int n = 0; n < 8; n++)
        #pragma unroll
        for (int c = 0; c < 4; c++) o[n][c] = 0.f;

    load_kv(0);

    for (int kt = 0; kt < 8; kt++) {
        if (kt + 1 < 8) { load_kv(kt + 1); CP_WAIT(1); }
        else            { CP_WAIT(0); }
        __syncthreads();

        const uint32_t kb = sb + 4*AQ_B + (kt & 1)*KVSTG;
        const uint32_t ckb  = sb + CK_O + (kt & 1)*256;
        const uint32_t padb = sb + CK_O + 512 + (kt & 1)*256;

        float ss[8][4], sc[8][4];
        #pragma unroll
        for (int n = 0; n < 8; n++)
            #pragma unroll
            for (int c = 0; c < 4; c++) { ss[n][c] = 0.f; sc[n][c] = 0.f; }

        #pragma unroll
        for (int j = 0; j < 4; j++) {
            const uint32_t ao = (wq + gg)*TSTR + j*32 + tt*4;
            uint32_t qsh[4], qsl[4], qch[4], qcl[4];
            qsh[0] = ld32s(sb + ao);            qsh[1] = ld32s(sb + ao + 8*TSTR);
            qsh[2] = ld32s(sb + ao + 16);       qsh[3] = ld32s(sb + ao + 8*TSTR + 16);
            qsl[0] = ld32s(sb + AQ_B + ao);     qsl[1] = ld32s(sb + AQ_B + ao + 8*TSTR);
            qsl[2] = ld32s(sb + AQ_B + ao + 16);qsl[3] = ld32s(sb + AQ_B + ao + 8*TSTR + 16);
            qch[0] = ld32s(sb + 2*AQ_B + ao);            qch[1] = ld32s(sb + 2*AQ_B + ao + 8*TSTR);
            qch[2] = ld32s(sb + 2*AQ_B + ao + 16);       qch[3] = ld32s(sb + 2*AQ_B + ao + 8*TSTR + 16);
            qcl[0] = ld32s(sb + 3*AQ_B + ao);            qcl[1] = ld32s(sb + 3*AQ_B + ao + 8*TSTR);
            qcl[2] = ld32s(sb + 3*AQ_B + ao + 16);       qcl[3] = ld32s(sb + 3*AQ_B + ao + 8*TSTR + 16);

            #pragma unroll
            for (int n = 0; n < 8; n++) {
                const uint32_t bo = (n*8 + gg)*TSTR + j*32 + tt*4;
                uint32_t ksh0 = ld32s(kb + bo),          ksh1 = ld32s(kb + bo + 16);
                uint32_t ksl0 = ld32s(kb + AK_B + bo),   ksl1 = ld32s(kb + AK_B + bo + 16);
                uint32_t kch0 = ld32s(kb + 2*AK_B + bo), kch1 = ld32s(kb + 2*AK_B + bo + 16);
                uint32_t kcl0 = ld32s(kb + 3*AK_B + bo), kcl1 = ld32s(kb + 3*AK_B + bo + 16);
                mma16816(ss[n], qsh, ksh0, ksh1);
                mma16816(ss[n], qsh, ksl0, ksl1);
                mma16816(ss[n], qsl, ksh0, ksh1);
                mma16816(sc[n], qch, kch0, kch1);
                mma16816(sc[n], qch, kcl0, kcl1);
                mma16816(sc[n], qcl, kch0, kch1);
            }
        }

        int   ckE[8], ckO[8];
        float pdE[8], pdO[8];
        #pragma unroll
        for (int n = 0; n < 8; n++) {
            ckE[n] = (int)ld32s(ckb + (n*8 + 2*tt)*4);
            ckO[n] = (int)ld32s(ckb + (n*8 + 2*tt + 1)*4);
            pdE[n] = ldf32s(padb + (n*8 + 2*tt)*4);
            pdO[n] = ldf32s(padb + (n*8 + 2*tt + 1)*4);
        }

        #pragma unroll
        for (int n = 0; n < 8; n++) {
            ss[n][0] = ((ckE[n]==cqA) ? ss[n][0] : sc[n][0]) * 0.125f + pdE[n];
            ss[n][1] = ((ckO[n]==cqA) ? ss[n][1] : sc[n][1]) * 0.125f + pdO[n];
            ss[n][2] = ((ckE[n]==cqB) ? ss[n][2] : sc[n][2]) * 0.125f + pdE[n];
            ss[n][3] = ((ckO[n]==cqB) ? ss[n][3] : sc[n][3]) * 0.125f + pdO[n];
        }

        float r0 = -1e30f, r1 = -1e30f;
        #pragma unroll
        for (int n = 0; n < 8; n++) {
            r0 = fmaxf(r0, fmaxf(ss[n][0], ss[n][1]));
            r1 = fmaxf(r1, fmaxf(ss[n][2], ss[n][3]));
        }
        r0 = fmaxf(r0, __shfl_xor_sync(0xffffffffu, r0, 1));
        r0 = fmaxf(r0, __shfl_xor_sync(0xffffffffu, r0, 2));
        r1 = fmaxf(r1, __shfl_xor_sync(0xffffffffu, r1, 1));
        r1 = fmaxf(r1, __shfl_xor_sync(0xffffffffu, r1, 2));

        float mn0 = fmaxf(m0, r0), mn1 = fmaxf(m1, r1);
        float al0 = __expf(m0 - mn0), al1 = __expf(m1 - mn1);
        m0 = mn0; m1 = mn1;

        float ts0 = 0.f, ts1 = 0.f;
        #pragma unroll
        for (int n = 0; n < 8; n++) {
            float vaE = (pdE[n] == 0.f) ? 1.f : 0.f;
            float vaO = (pdO[n] == 0.f) ? 1.f : 0.f;
            float e0 = __expf(ss[n][0] - mn0) * vaE;
            float e1 = __expf(ss[n][1] - mn0) * vaO;
            float e2 = __expf(ss[n][2] - mn1) * vaE;
            float e3 = __expf(ss[n][3] - mn1) * vaO;
            ts0 += e0 + e1; ts1 += e2 + e3;
            float p0 = (ckE[n]==cqA) ? e0 : 0.f;
            float p1 = (ckO[n]==cqA) ? e1 : 0.f;
            float p2 = (ckE[n]==cqB) ? e2 : 0.f;
            float p3 = (ckO[n]==cqB) ? e3 : 0.f;
            sc[n][0] = e0 - p0; sc[n][1] = e1 - p1; sc[n][2] = e2 - p2; sc[n][3] = e3 - p3;
            ss[n][0] = p0; ss[n][1] = p1; ss[n][2] = p2; ss[n][3] = p3;
        }
        ts0 += __shfl_xor_sync(0xffffffffu, ts0, 1);
        ts0 += __shfl_xor_sync(0xffffffffu, ts0, 2);
        ts1 += __shfl_xor_sync(0xffffffffu, ts1, 1);
        ts1 += __shfl_xor_sync(0xffffffffu, ts1, 2);
        l0 = l0 * al0 + ts0;
        l1 = l1 * al1 + ts1;

        #pragma unroll
        for (int n = 0; n < 8; n++) {
            o[n][0] *= al0; o[n][1] *= al0; o[n][2] *= al1; o[n][3] *= al1;
        }

        #pragma unroll
        for (int j = 0; j < 4; j++) {
            const int n0t = 2*j, n1t = 2*j + 1;
            uint32_t ash[4], asl[4], ach[4], acl[4];
            {
                float p00 = ss[n0t][0], p01 = ss[n0t][1], p02 = ss[n0t][2], p03 = ss[n0t][3];
                float p10 = ss[n1t][0], p11 = ss[n1t][1], p12 = ss[n1t][2], p13 = ss[n1t][3];
                ash[0] = pack_bf2(p00, p01); ash[1] = pack_bf2(p02, p03);
                ash[2] = pack_bf2(p10, p11); ash[3] = pack_bf2(p12, p13);
                __nv_bfloat162* t;
                t = (__nv_bfloat162*)&ash[0];
                asl[0] = pack_bf2(p00 - __bfloat162float(t->x), p01 - __bfloat162float(t->y));
                t = (__nv_bfloat162*)&ash[1];
                asl[1] = pack_bf2(p02 - __bfloat162float(t->x), p03 - __bfloat162float(t->y));
                t = (__nv_bfloat162*)&ash[2];
                asl[2] = pack_bf2(p10 - __bfloat162float(t->x), p11 - __bfloat162float(t->y));
                t = (__nv_bfloat162*)&ash[3];
                asl[3] = pack_bf2(p12 - __bfloat162float(t->x), p13 - __bfloat162float(t->y));

                float c00 = sc[n0t][0], c01 = sc[n0t][1], c02 = sc[n0t][2], c03 = sc[n0t][3];
                float c10 = sc[n1t][0], c11 = sc[n1t][1], c12 = sc[n1t][2], c13 = sc[n1t][3];
                ach[0] = pack_bf2(c00, c01); ach[1] = pack_bf2(c02, c03);
                ach[2] = pack_bf2(c10, c11); ach[3] = pack_bf2(c12, c13);
                t = (__nv_bfloat162*)&ach[0];
                acl[0] = pack_bf2(c00 - __bfloat162float(t->x), c01 - __bfloat162float(t->y));
                t = (__nv_bfloat162*)&ach[1];
                acl[1] = pack_bf2(c02 - __bfloat162float(t->x), c03 - __bfloat162float(t->y));
                t = (__nv_bfloat162*)&ach[2];
                acl[2] = pack_bf2(c10 - __bfloat162float(t->x), c11 - __bfloat162float(t->y));
                t = (__nv_bfloat162*)&ach[3];
                acl[3] = pack_bf2(c12 - __bfloat162float(t->x), c13 - __bfloat162float(t->y));
            }
            #pragma unroll
            for (int n = 0; n < 8; n++) {
                const uint32_t vo = (n*8 + gg)*TSTR + j*32 + tt*4;
                uint32_t vsh0 = ld32s(kb + 4*AK_B + vo), vsh1 = ld32s(kb + 4*AK_B + vo + 16);
                uint32_t vsl0 = ld32s(kb + 5*AK_B + vo), vsl1 = ld32s(kb + 5*AK_B + vo + 16);
                uint32_t vch0 = ld32s(kb + 6*AK_B + vo), vch1 = ld32s(kb + 6*AK_B + vo + 16);
                uint32_t vcl0 = ld32s(kb + 7*AK_B + vo), vcl1 = ld32s(kb + 7*AK_B + vo + 16);
                mma16816(o[n], ash, vsh0, vsh1);
                mma16816(o[n], ash, vsl0, vsl1);
                mma16816(o[n], asl, vsh0, vsh1);
                mma16816(o[n], ach, vch0, vch1);
                mma16816(o[n], ach, vcl0, vcl1);
                mma16816(o[n], acl, vch0, vch1);
            }
        }
        __syncthreads();
    }

    float li0 = (l0 > 0.f) ? (1.f / l0) : 0.f;
    float li1 = (l1 > 0.f) ? (1.f / l1) : 0.f;
    const size_t rA = (size_t)(b*512 + q0 + wq + gg) * DM + h*64;
    const size_t rB = rA + (size_t)8 * DM;
    #pragma unroll
    for (int n = 0; n < 8; n++) {
        int colg = n*8 + 2*tt;
        float v0 = o[n][0]*li0, v1 = o[n][1]*li0, v2 = o[n][2]*li1, v3 = o[n][3]*li1;
        uint32_t h0 = pack_bf2(v0, v1), h1 = pack_bf2(v2, v3);
        __nv_bfloat162* t0 = (__nv_bfloat162*)&h0;
        __nv_bfloat162* t1 = (__nv_bfloat162*)&h1;
        uint32_t lo0 = pack_bf2(v0 - __bfloat162float(t0->x), v1 - __bfloat162float(t0->y));
        uint32_t lo1 = pack_bf2(v2 - __bfloat162float(t1->x), v3 - __bfloat162float(t1->y));
        *(uint32_t*)(g_ath + rA + colg) = h0;
        *(uint32_t*)(g_atl + rA + colg) = lo0;
        *(uint32_t*)(g_ath + rB + colg) = h1;
        *(uint32_t*)(g_atl + rB + colg) = lo1;
    }
}

// ---------------- launch ----------------
extern "C" void kernel_launch(void* const* d_in, const int* in_sizes, int n_in,
                              void* d_out, int out_size)
{
    const float *x, *Wqs, *Wks, *Wvs, *Wqc, *Wkc, *Wvc, *Wo;
    const int *chain, *amask;

    if (in_sizes[0] == MROWS * DM) {
        x     = (const float*)d_in[0];
        chain = (const int*)d_in[1];
        amask = (const int*)d_in[2];
        Wqs = (const float*)d_in[3]; Wks = (const float*)d_in[4]; Wvs = (const float*)d_in[5];
        Wqc = (const float*)d_in[6]; Wkc = (const float*)d_in[7]; Wvc = (const float*)d_in[8];
        Wo  = (const float*)d_in[9];
    } else {
        Wkc = (const float*)d_in[0]; Wks = (const float*)d_in[1]; Wo  = (const float*)d_in[2];
        Wqc = (const float*)d_in[3]; Wqs = (const float*)d_in[4];
        Wvc = (const float*)d_in[5]; Wvs = (const float*)d_in[6];
        amask = (const int*)d_in[7]; chain = (const int*)d_in[8];
        x     = (const float*)d_in[9];
    }

    float *qs, *ks, *vs, *qc, *kc, *vc;
    cudaGetSymbolAddress((void**)&qs, g_qs);
    cudaGetSymbolAddress((void**)&ks, g_ks);
    cudaGetSymbolAddress((void**)&vs, g_vs);
    cudaGetSymbolAddress((void**)&qc, g_qc);
    cudaGetSymbolAddress((void**)&kc, g_kc);
    cudaGetSymbolAddress((void**)&vc, g_vc);
    __nv_bfloat16 *xh, *xl, *wth, *wtl, *ath, *atl;
    cudaGetSymbolAddress((void**)&xh,  g_xh);
    cudaGetSymbolAddress((void**)&xl,  g_xl);
    cudaGetSymbolAddress((void**)&wth, g_wth);
    cudaGetSymbolAddress((void**)&wtl, g_wtl);
    cudaGetSymbolAddress((void**)&ath, g_ath);
    cudaGetSymbolAddress((void**)&atl, g_atl);

    AttnP ap;
    {
        void* p;
        cudaGetSymbolAddress(&p, g_qsh);  ap.q0 = (const __nv_bfloat16*)p;
        cudaGetSymbolAddress(&p, g_qsl);  ap.q1 = (const __nv_bfloat16*)p;
        cudaGetSymbolAddress(&p, g_qch);  ap.q2 = (const __nv_bfloat16*)p;
        cudaGetSymbolAddress(&p, g_qcl);  ap.q3 = (const __nv_bfloat16*)p;
        cudaGetSymbolAddress(&p, g_ksh);  ap.k0 = (const __nv_bfloat16*)p;
        cudaGetSymbolAddress(&p, g_ksl);  ap.k1 = (const __nv_bfloat16*)p;
        cudaGetSymbolAddress(&p, g_kch);  ap.k2 = (const __nv_bfloat16*)p;
        cudaGetSymbolAddress(&p, g_kcl);  ap.k3 = (const __nv_bfloat16*)p;
        cudaGetSymbolAddress(&p, g_vsth); ap.v0 = (const __nv_bfloat16*)p;
        cudaGetSymbolAddress(&p, g_vstl); ap.v1 = (const __nv_bfloat16*)p;
        cudaGetSymbolAddress(&p, g_vcth); ap.v2 = (const __nv_bfloat16*)p;
        cudaGetSymbolAddress(&p, g_vctl); ap.v3 = (const __nv_bfloat16*)p;
    }
    ap.chain = chain; ap.amask = amask;

    // 1) merged prep (x split + weight transpose/split + rope table)
    W7 ws; ws.w[0]=Wqs; ws.w[1]=Wks; ws.w[2]=Wvs; ws.w[3]=Wqc; ws.w[4]=Wkc; ws.w[5]=Wvc; ws.w[6]=Wo;
    prep_all<<<4096 + 7168 + 64, 256>>>(x, ws);

    // 2) six projections on tensor cores (exact R5)
    cudaFuncSetAttribute(mma_gemm, cudaFuncAttributeMaxDynamicSharedMemorySize, GEMM_SMEM);
    TCGemm gp;
    gp.Ah = xh; gp.Al = xl; gp.Bh = wth; gp.Bl = wtl;
    gp.C[0]=qs; gp.C[1]=ks; gp.C[2]=vs; gp.C[3]=qc; gp.C[4]=kc; gp.C[5]=vc;
    mma_gemm<<<dim3(8, 32, 6), 256, GEMM_SMEM>>>(gp);

    // 3) merged rope/split + V transpose/split
    qv_prep<<<8192 + 8192, 256>>>();

    // 4) attention (exact R5)
    cudaFuncSetAttribute(attn_mma, cudaFuncAttributeMaxDynamicSharedMemorySize, AT_SMEM);
    attn_mma<<<dim3(4, 16, 8), 256, AT_SMEM>>>(ap);

    // 5) output projection
    TCGemm go;
    go.Ah = ath; go.Al = atl; go.Bh = wth + (size_t)6*DM*DM; go.Bl = wtl + (size_t)6*DM*DM;
    go.C[0] = (float*)d_out;
    for (int i = 1; i < 6; i++) go.C[i] = (float*)d_out;
    mma_gemm<<<dim3(8, 32, 1), 256, GEMM_SMEM>>>(go);
}

// round 13
// speedup vs baseline: 1.0682x; 1.0218x over previous
#include <cuda_runtime.h>
#include <cuda_bf16.h>
#include <math.h>
#include <stdint.h>

#define MROWS 4096          // B*S
#define DM    1024          // D_MODEL = INNER

// ---------------- scratch ----------------
__device__ float g_qs[MROWS*DM];
__device__ float g_ks[MROWS*DM];
__device__ float g_vs[MROWS*DM];
__device__ float g_qc[MROWS*DM];
__device__ float g_kc[MROWS*DM];
__device__ float g_vc[MROWS*DM];

__device__ __nv_bfloat16 g_xh[MROWS*DM];
__device__ __nv_bfloat16 g_xl[MROWS*DM];
__device__ __nv_bfloat16 g_wth[7*DM*DM];
__device__ __nv_bfloat16 g_wtl[7*DM*DM];
__device__ __nv_bfloat16 g_ath[MROWS*DM];
__device__ __nv_bfloat16 g_atl[MROWS*DM];

__device__ __nv_bfloat16 g_qsh[MROWS*DM];
__device__ __nv_bfloat16 g_qsl[MROWS*DM];
__device__ __nv_bfloat16 g_ksh[MROWS*DM];
__device__ __nv_bfloat16 g_ksl[MROWS*DM];
__device__ __nv_bfloat16 g_qch[MROWS*DM];
__device__ __nv_bfloat16 g_qcl[MROWS*DM];
__device__ __nv_bfloat16 g_kch[MROWS*DM];
__device__ __nv_bfloat16 g_kcl[MROWS*DM];
__device__ __nv_bfloat16 g_vsth[MROWS*DM];
__device__ __nv_bfloat16 g_vstl[MROWS*DM];
__device__ __nv_bfloat16 g_vcth[MROWS*DM];
__device__ __nv_bfloat16 g_vctl[MROWS*DM];

__device__ float g_cos[512*32];
__device__ float g_sin[512*32];

// ---------------- helpers ----------------
__device__ __forceinline__ uint32_t smem_u32(const void* p) {
    uint32_t a;
    asm("{ .reg .u64 t; cvta.to.shared.u64 t, %1; cvt.u32.u64 %0, t; }" : "=r"(a) : "l"(p));
    return a;
}
#define CP16(dst, src)    asm volatile("cp.async.cg.shared.global [%0], [%1], 16;" :: "r"(dst), "l"(src) : "memory")
#define CP_COMMIT()       asm volatile("cp.async.commit_group;" ::: "memory")
#define CP_WAIT(n)        asm volatile("cp.async.wait_group %0;" :: "n"(n) : "memory")

__device__ __forceinline__ uint32_t ld32s(uint32_t a) {
    uint32_t v;
    asm volatile("ld.shared.b32 %0, [%1];" : "=r"(v) : "r"(a));
    return v;
}
__device__ __forceinline__ float ldf32s(uint32_t a) {
    float v;
    asm volatile("ld.shared.f32 %0, [%1];" : "=f"(v) : "r"(a));
    return v;
}
__device__ __forceinline__ void mma16816(float* c, const uint32_t* a, uint32_t b0, uint32_t b1) {
    asm volatile("mma.sync.aligned.m16n8k16.row.col.f32.bf16.bf16.f32 "
        "{%0,%1,%2,%3}, {%4,%5,%6,%7}, {%8,%9}, {%0,%1,%2,%3};"
        : "+f"(c[0]), "+f"(c[1]), "+f"(c[2]), "+f"(c[3])
        : "r"(a[0]), "r"(a[1]), "r"(a[2]), "r"(a[3]), "r"(b0), "r"(b1));
}
__device__ __forceinline__ uint32_t pack_bf2(float a, float b) {
    __nv_bfloat162 t;
    t.x = __float2bfloat16(a); t.y = __float2bfloat16(b);
    return *(uint32_t*)&t;
}

// ---------------- merged prep 1 ----------------
struct W7 { const float* w[7]; };

__global__ __launch_bounds__(256) void prep_all(const float* __restrict__ x, W7 ws)
{
    __shared__ float tile[32][33];
    const int bx = blockIdx.x, tid = threadIdx.x;

    if (bx < 4096) {
        int i = bx * 256 + tid;
        float4 v = *(const float4*)(x + (size_t)i * 4);
        __nv_bfloat16 h0 = __float2bfloat16(v.x), h1 = __float2bfloat16(v.y);
        __nv_bfloat16 h2 = __float2bfloat16(v.z), h3 = __float2bfloat16(v.w);
        __nv_bfloat16 l0 = __float2bfloat16(v.x - __bfloat162float(h0));
        __nv_bfloat16 l1 = __float2bfloat16(v.y - __bfloat162float(h1));
        __nv_bfloat16 l2 = __float2bfloat16(v.z - __bfloat162float(h2));
        __nv_bfloat16 l3 = __float2bfloat16(v.w - __bfloat162float(h3));
        __nv_bfloat162 hA = {h0, h1}, hB = {h2, h3}, lA = {l0, l1}, lB = {l2, l3};
        uint2 hp, lp;
        hp.x = *(uint32_t*)&hA; hp.y = *(uint32_t*)&hB;
        lp.x = *(uint32_t*)&lA; lp.y = *(uint32_t*)&lB;
        *(uint2*)((uint16_t*)g_xh + (size_t)i * 4) = hp;
        *(uint2*)((uint16_t*)g_xl + (size_t)i * 4) = lp;
    } else if (bx < 4096 + 7168) {
        int rem = bx - 4096;
        int bz = rem >> 10;
        rem &= 1023;
        int n0 = (rem & 31) * 32, k0 = (rem >> 5) * 32;
        int tx = tid & 31, ty = tid >> 5;
        const float* W = ws.w[bz];
        __nv_bfloat16* oh = g_wth + (size_t)bz * DM * DM;
        __nv_bfloat16* ol = g_wtl + (size_t)bz * DM * DM;
        #pragma unroll
        for (int j = 0; j < 4; j++)
            tile[ty + j*8][tx] = W[(size_t)(k0 + ty + j*8) * DM + n0 + tx];
        __syncthreads();
        #pragma unroll
        for (int j = 0; j < 4; j++) {
            float v = tile[tx][ty + j*8];
            __nv_bfloat16 h = __float2bfloat16(v);
            __nv_bfloat16 l = __float2bfloat16(v - __bfloat162float(h));
            size_t o = (size_t)(n0 + ty + j*8) * DM + k0 + tx;
            oh[o] = h; ol[o] = l;
        }
    } else {
        int p = (bx - 11264) * 256 + tid;
        int i = p & 31, s = p >> 5;
        float inv_freq = powf(10000.0f, -((float)(2*i)) * (1.0f/64.0f));
        float f = (float)s * inv_freq;
        double sd, cd; sincos((double)f, &sd, &cd);
        g_cos[p] = (float)cd; g_sin[p] = (float)sd;
    }
}

// ---------------- merged prep 2 ----------------
__global__ __launch_bounds__(256) void qv_prep()
{
    __shared__ float t[32][33];
    const int bx = blockIdx.x, tid = threadIdx.x;

    if (bx < 8192) {
        int p = bx * 256 + tid;
        int i = p & 31, h = (p >> 5) & 15, row = p >> 9, s = row & 511;
        float c  = g_cos[(s << 5) + i];
        float sn = g_sin[(s << 5) + i];
        int base = row * DM + h * 64 + i;

        float q0 = g_qs[base], q1 = g_qs[base + 32];
        float k0 = g_ks[base], k1 = g_ks[base + 32];
        float qr0 = q0 * c - q1 * sn, qr1 = q1 * c + q0 * sn;
        float kr0 = k0 * c - k1 * sn, kr1 = k1 * c + k0 * sn;
        float qc0 = g_qc[base], qc1 = g_qc[base + 32];
        float kc0 = g_kc[base], kc1 = g_kc[base + 32];

        #define SPLIT_ST(arrh, arrl, idx, v) do { \
            __nv_bfloat16 _h = __float2bfloat16(v); \
            arrh[idx] = _h; arrl[idx] = __float2bfloat16((v) - __bfloat162float(_h)); } while (0)
        SPLIT_ST(g_qsh, g_qsl, base, qr0);      SPLIT_ST(g_qsh, g_qsl, base + 32, qr1);
        SPLIT_ST(g_ksh, g_ksl, base, kr0);      SPLIT_ST(g_ksh, g_ksl, base + 32, kr1);
        SPLIT_ST(g_qch, g_qcl, base, qc0);      SPLIT_ST(g_qch, g_qcl, base + 32, qc1);
        SPLIT_ST(g_kch, g_kcl, base, kc0);      SPLIT_ST(g_kch, g_kcl, base + 32, kc1);
        #undef SPLIT_ST
    } else {
        int rem = bx - 8192;
        int c0 = (rem & 31) * 32;
        int s0 = ((rem >> 5) & 15) * 32;
        int z  = rem >> 9;
        int b = z >> 1, w = z & 1;
        int tx = tid & 31, ty = tid >> 5;
        const float* src = w ? g_vc : g_vs;
        __nv_bfloat16* oh = w ? g_vcth : g_vsth;
        __nv_bfloat16* ol = w ? g_vctl : g_vstl;
        #pragma unroll
        for (int j = 0; j < 4; j++)
            t[ty + j*8][tx] = src[(size_t)(b*512 + s0 + ty + j*8) * DM + c0 + tx];
        __syncthreads();
        #pragma unroll
        for (int j = 0; j < 4; j++) {
            float v = t[tx][ty + j*8];
            __nv_bfloat16 h = __float2bfloat16(v);
            __nv_bfloat16 l = __float2bfloat16(v - __bfloat162float(h));
            size_t o = (size_t)(b*1024 + c0 + ty + j*8) * 512 + s0 + tx;
            oh[o] = h; ol[o] = l;
        }
    }
}

// ---------------- mma.sync split-bf16 GEMM (EXACT R5, validated) ----------------
#define ROWB  112
#define BUFB  (128*ROWB)
#define STGB  (4*BUFB)
#define GEMM_SMEM (2*STGB)           // 114688 -> 2 CTAs/SM

struct TCGemm {
    const __nv_bfloat16 *Ah, *Al, *Bh, *Bl;
    float* C[6];
};

__global__ __launch_bounds__(256) void mma_gemm(TCGemm g)
{
    extern __shared__ char smem[];
    const uint32_t sb = smem_u32(smem);

    const int tid = threadIdx.x, wid = tid >> 5, lane = tid & 31;
    const int n0 = blockIdx.x * 128, m0 = blockIdx.y * 128, z = blockIdx.z;
    const int wm = wid & 1, wn = wid >> 1;
    const int gg = lane >> 2, tt = lane & 3;

    const __nv_bfloat16* bps[4];
    bps[0] = g.Ah + (size_t)m0 * DM;
    bps[1] = g.Al + (size_t)m0 * DM;
    bps[2] = g.Bh + (size_t)z * DM * DM + (size_t)n0 * DM;
    bps[3] = g.Bl + (size_t)z * DM * DM + (size_t)n0 * DM;

    auto load_stage = [&](int s, int kc) {
        uint32_t base = sb + s * STGB;
        #pragma unroll
        for (int buf = 0; buf < 4; buf++) {
            const __nv_bfloat16* bp = bps[buf] + kc * 32;
            #pragma unroll
            for (int it = 0; it < 2; it++) {
                int idx = it * 256 + tid;
                int r = idx >> 2, c = idx & 3;
                CP16(base + buf * BUFB + r * ROWB + c * 16, bp + (size_t)r * DM + c * 8);
            }
        }
        CP_COMMIT();
    };

    float acc[4][4][4];
    #pragma unroll
    for (int i = 0; i < 4; i++)
        #pragma unroll
        for (int j = 0; j < 4; j++)
            #pragma unroll
            for (int k = 0; k < 4; k++) acc[i][j][k] = 0.f;

    load_stage(0, 0);

    for (int s = 0; s < 32; s++) {
        if (s + 1 < 32) { load_stage((s + 1) & 1, s + 1); CP_WAIT(1); }
        else            { CP_WAIT(0); }
        __syncthreads();

        const uint32_t stg = sb + (s & 1) * STGB;
        const uint32_t ahB = stg, alB = stg + BUFB, bhB = stg + 2*BUFB, blB = bhB + BUFB;

        #pragma unroll
        for (int kk = 0; kk < 2; kk++) {
            const uint32_t kOff = (kk * 16 + 2 * tt) * 2;

            uint32_t a_h[4][4], a_l[4][4];
            #pragma unroll
            for (int mf = 0; mf < 4; mf++) {
                uint32_t o0 = (wm*64 + mf*16 + gg) * ROWB + kOff;
                a_h[mf][0] = ld32s(ahB + o0);
                a_h[mf][1] = ld32s(ahB + o0 + 8*ROWB);
                a_h[mf][2] = ld32s(ahB + o0 + 16);
                a_h[mf][3] = ld32s(ahB + o0 + 8*ROWB + 16);
                a_l[mf][0] = ld32s(alB + o0);
                a_l[mf][1] = ld32s(alB + o0 + 8*ROWB);
                a_l[mf][2] = ld32s(alB + o0 + 16);
                a_l[mf][3] = ld32s(alB + o0 + 8*ROWB + 16);
            }
            #pragma unroll
            for (int nf = 0; nf < 4; nf++) {
                uint32_t o = (wn*32 + nf*8 + gg) * ROWB + kOff;
                uint32_t bh0 = ld32s(bhB + o), bh1 = ld32s(bhB + o + 16);
                uint32_t bl0 = ld32s(blB + o), bl1 = ld32s(blB + o + 16);
                #pragma unroll
                for (int mf = 0; mf < 4; mf++) {
                    mma16816(acc[mf][nf], a_h[mf], bh0, bh1);
                    mma16816(acc[mf][nf], a_h[mf], bl0, bl1);
                    mma16816(acc[mf][nf], a_l[mf], bh0, bh1);
                }
            }
        }
        __syncthreads();
    }

    float* C = g.C[z];
    #pragma unroll
    for (int mf = 0; mf < 4; mf++) {
        int row0 = m0 + wm*64 + mf*16 + gg;
        #pragma unroll
        for (int nf = 0; nf < 4; nf++) {
            int col = n0 + wn*32 + nf*8 + 2*tt;
            *(float2*)(C + (size_t)row0 * DM + col)       = make_float2(acc[mf][nf][0], acc[mf][nf][1]);
            *(float2*)(C + (size_t)(row0 + 8) * DM + col) = make_float2(acc[mf][nf][2], acc[mf][nf][3]);
        }
    }
}

// ---------------- attention v2: 64 q-rows, 128 threads, single-buffer KV, 2 CTA/SM ----------------
#define TSTR   144
#define AQ_B2  (64*TSTR)             // 9216
#define KV_O   (4*AQ_B2)             // 36864
#define CK_O2  (KV_O + 8*AQ_B2)      // 110592
#define AT_SMEM2 (CK_O2 + 768)       // 111360 -> 2 CTAs/SM

struct AttnP {
    const __nv_bfloat16 *q0, *q1, *q2, *q3;
    const __nv_bfloat16 *k0, *k1, *k2, *k3;
    const __nv_bfloat16 *v0, *v1, *v2, *v3;
    const int* chain;
    const int* amask;
};

__global__ __launch_bounds__(128, 2) void attn_mma(AttnP P)
{
    extern __shared__ char smem[];
    const uint32_t sb = smem_u32(smem);

    const int tid = threadIdx.x, wid = tid >> 5, lane = tid & 31;
    const int gg = lane >> 2, tt = lane & 3;
    const int qt = blockIdx.x, h = blockIdx.y, b = blockIdx.z;
    const int q0 = qt * 64;
    const int wq = wid * 16;          // wid in [0,4): 64 rows

    // Q tiles (once): 4 bufs x 64 rows x 8 chunks = 512 CP16/buf, 128 thr -> 4 its
    auto ldQ = [&](const __nv_bfloat16* gp, uint32_t so) {
        #pragma unroll
        for (int it = 0; it < 4; it++) {
            int idx = it * 128 + tid, r = idx >> 3, c = idx & 7;
            CP16(sb + so + r*TSTR + c*16,
                 gp + (size_t)(b*512 + q0 + r) * DM + h*64 + c*8);
        }
    };
    ldQ(P.q0, 0); ldQ(P.q1, AQ_B2); ldQ(P.q2, 2*AQ_B2); ldQ(P.q3, 3*AQ_B2);

    auto load_kv = [&](int kt) {
        const uint32_t base = sb + KV_O;
        const int k0g = kt * 64;
        auto ldK = [&](const __nv_bfloat16* gp, uint32_t so) {
            #pragma unroll
            for (int it = 0; it < 4; it++) {
                int idx = it * 128 + tid, r = idx >> 3, c = idx & 7;
                CP16(base + so + r*TSTR + c*16,
                     gp + (size_t)(b*512 + k0g + r) * DM + h*64 + c*8);
            }
        };
        auto ldV = [&](const __nv_bfloat16* gp, uint32_t so) {
            #pragma unroll
            for (int it = 0; it < 4; it++) {
                int idx = it * 128 + tid, r = idx >> 3, c = idx & 7;
                CP16(base + so + r*TSTR + c*16,
                     gp + (size_t)(b*1024 + h*64 + r) * 512 + k0g + c*8);
            }
        };
        ldK(P.k0, 0);       ldK(P.k1, AQ_B2);   ldK(P.k2, 2*AQ_B2); ldK(P.k3, 3*AQ_B2);
        ldV(P.v0, 4*AQ_B2); ldV(P.v1, 5*AQ_B2); ldV(P.v2, 6*AQ_B2); ldV(P.v3, 7*AQ_B2);
        if (tid < 64) {
            int ck = P.chain[b*512 + k0g + tid];
            float pv = (P.amask[b*512 + k0g + tid] != 0) ? 0.0f : -1e30f;
            ((int*)  (smem))[ CK_O2/4 + tid ] = ck;
            ((float*)(smem))[ (CK_O2 + 256)/4 + tid ] = pv;
        }
        CP_COMMIT();
    };

    const int sA = q0 + wq + gg;
    const int cqA = P.chain[b*512 + sA];
    const int cqB = P.chain[b*512 + sA + 8];

    float m0 = -1e30f, m1 = -1e30f, l0 = 0.f, l1 = 0.f;
    float o[8][4];
    #pragma unroll
    for (int n = 0; n < 8; n++)
        #pragma unroll
        for (int c = 0; c < 4; c++) o[n][c] = 0.f;

    load_kv(0);

    for (int kt = 0; kt < 8; kt++) {
        CP_WAIT(0);
        __syncthreads();

        const uint32_t kb   = sb + KV_O;
        const uint32_t ckb  = sb + CK_O2;
        const uint32_t padb = sb + CK_O2 + 256;

        float ss[8][4], sc[8][4];
        #pragma unroll
        for (int n = 0; n < 8; n++)
            #pragma unroll
            for (int c = 0; c < 4; c++) { ss[n][c] = 0.f; sc[n][c] = 0.f; }

        #pragma unroll
        for (int j = 0; j < 4; j++) {
            const uint32_t ao = (wq + gg)*TSTR + j*32 + tt*4;
            uint32_t qsh[4], qsl[4], qch[4], qcl[4];
            qsh[0] = ld32s(sb + ao);             qsh[1] = ld32s(sb + ao + 8*TSTR);
            qsh[2] = ld32s(sb + ao + 16);        qsh[3] = ld32s(sb + ao + 8*TSTR + 16);
            qsl[0] = ld32s(sb + AQ_B2 + ao);     qsl[1] = ld32s(sb + AQ_B2 + ao + 8*TSTR);
            qsl[2] = ld32s(sb + AQ_B2 + ao + 16);qsl[3] = ld32s(sb + AQ_B2 + ao + 8*TSTR + 16);
            qch[0] = ld32s(sb + 2*AQ_B2 + ao);            qch[1] = ld32s(sb + 2*AQ_B2 + ao + 8*TSTR);
            qch[2] = ld32s(sb + 2*AQ_B2 + ao + 16);       qch[3] = ld32s(sb + 2*AQ_B2 + ao + 8*TSTR + 16);
            qcl[0] = ld32s(sb + 3*AQ_B2 + ao);            qcl[1] = ld32s(sb + 3*AQ_B2 + ao + 8*TSTR);
            qcl[2] = ld32s(sb + 3*AQ_B2 + ao + 16);       qcl[3] = ld32s(sb + 3*AQ_B2 + ao + 8*TSTR + 16);

            #pragma unroll
            for (int n = 0; n < 8; n++) {
                const uint32_t bo = (n*8 + gg)*TSTR + j*32 + tt*4;
                uint32_t ksh0 = ld32s(kb + bo),           ksh1 = ld32s(kb + bo + 16);
                uint32_t ksl0 = ld32s(kb + AQ_B2 + bo),   ksl1 = ld32s(kb + AQ_B2 + bo + 16);
                uint32_t kch0 = ld32s(kb + 2*AQ_B2 + bo), kch1 = ld32s(kb + 2*AQ_B2 + bo + 16);
                uint32_t kcl0 = ld32s(kb + 3*AQ_B2 + bo), kcl1 = ld32s(kb + 3*AQ_B2 + bo + 16);
                mma16816(ss[n], qsh, ksh0, ksh1);
                mma16816(ss[n], qsh, ksl0, ksl1);
                mma16816(ss[n], qsl, ksh0, ksh1);
                mma16816(sc[n], qch, kch0, kch1);
                mma16816(sc[n], qch, kcl0, kcl1);
                mma16816(sc[n], qcl, kch0, kch1);
            }
        }

        int   ckE[8], ckO[8];
        float pdE[8], pdO[8];
        #pragma unroll
        for (int n = 0; n < 8; n++) {
            ckE[n] = (int)ld32s(ckb + (n*8 + 2*tt)*4);
            ckO[n] = (int)ld32s(ckb + (n*8 + 2*tt + 1)*4);
            pdE[n] = ldf32s(padb + (n*8 + 2*tt)*4);
            pdO[n] = ldf32s(padb + (n*8 + 2*tt + 1)*4);
        }

        #pragma unroll
        for (int n = 0; n < 8; n++) {
            ss[n][0] = ((ckE[n]==cqA) ? ss[n][0] : sc[n][0]) * 0.125f + pdE[n];
            ss[n][1] = ((ckO[n]==cqA) ? ss[n][1] : sc[n][1]) * 0.125f + pdO[n];
            ss[n][2] = ((ckE[n]==cqB) ? ss[n][2] : sc[n][2]) * 0.125f + pdE[n];
            ss[n][3] = ((ckO[n]==cqB) ? ss[n][3] : sc[n][3]) * 0.125f + pdO[n];
        }

        float r0 = -1e30f, r1 = -1e30f;
        #pragma unroll
        for (int n = 0; n < 8; n++) {
            r0 = fmaxf(r0, fmaxf(ss[n][0], ss[n][1]));
            r1 = fmaxf(r1, fmaxf(ss[n][2], ss[n][3]));
        }
        r0 = fmaxf(r0, __shfl_xor_sync(0xffffffffu, r0, 1));
        r0 = fmaxf(r0, __shfl_xor_sync(0xffffffffu, r0, 2));
        r1 = fmaxf(r1, __shfl_xor_sync(0xffffffffu, r1, 1));
        r1 = fmaxf(r1, __shfl_xor_sync(0xffffffffu, r1, 2));

        float mn0 = fmaxf(m0, r0), mn1 = fmaxf(m1, r1);
        float al0 = __expf(m0 - mn0), al1 = __expf(m1 - mn1);
        m0 = mn0; m1 = mn1;

        float ts0 = 0.f, ts1 = 0.f;
        #pragma unroll
        for (int n = 0; n < 8; n++) {
            float vaE = (pdE[n] == 0.f) ? 1.f : 0.f;
            float vaO = (pdO[n] == 0.f) ? 1.f : 0.f;
            float e0 = __expf(ss[n][0] - mn0) * vaE;
            float e1 = __expf(ss[n][1] - mn0) * vaO;
            float e2 = __expf(ss[n][2] - mn1) * vaE;
            float e3 = __expf(ss[n][3] - mn1) * vaO;
            ts0 += e0 + e1; ts1 += e2 + e3;
            float p0 = (ckE[n]==cqA) ? e0 : 0.f;
            float p1 = (ckO[n]==cqA) ? e1 : 0.f;
            float p2 = (ckE[n]==cqB) ? e2 : 0.f;
            float p3 = (ckO[n]==cqB) ? e3 : 0.f;
            sc[n][0] = e0 - p0; sc[n][1] = e1 - p1; sc[n][2] = e2 - p2; sc[n][3] = e3 - p3;
            ss[n][0] = p0; ss[n][1] = p1; ss[n][2] = p2; ss[n][3] = p3;
        }
        ts0 += __shfl_xor_sync(0xffffffffu, ts0, 1);
        ts0 += __shfl_xor_sync(0xffffffffu, ts0, 2);
        ts1 += __shfl_xor_sync(0xffffffffu, ts1, 1);
        ts1 += __shfl_xor_sync(0xffffffffu, ts1, 2);
        l0 = l0 * al0 + ts0;
        l1 = l1 * al1 + ts1;

        #pragma unroll
        for (int n = 0; n < 8; n++) {
            o[n][0] *= al0; o[n][1] *= al0; o[n][2] *= al1; o[n][3] *= al1;
        }

        #pragma unroll
        for (int j = 0; j < 4; j++) {
            const int n0t = 2*j, n1t = 2*j + 1;
            uint32_t ash[4], asl[4], ach[4], acl[4];
            {
                float p00 = ss[n0t][0], p01 = ss[n0t][1], p02 = ss[n0t][2], p03 = ss[n0t][3];
                float p10 = ss[n1t][0], p11 = ss[n1t][1], p12 = ss[n1t][2], p13 = ss[n1t][3];
                ash[0] = pack_bf2(p00, p01); ash[1] = pack_bf2(p02, p03);
                ash[2] = pack_bf2(p10, p11); ash[3] = pack_bf2(p12, p13);
                __nv_bfloat162* t;
                t = (__nv_bfloat162*)&ash[0];
                asl[0] = pack_bf2(p00 - __bfloat162float(t->x), p01 - __bfloat162float(t->y));
                t = (__nv_bfloat162*)&ash[1];
                asl[1] = pack_bf2(p02 - __bfloat162float(t->x), p03 - __bfloat162float(t->y));
                t = (__nv_bfloat162*)&ash[2];
                asl[2] = pack_bf2(p10 - __bfloat162float(t->x), p11 - __bfloat162float(t->y));
                t = (__nv_bfloat162*)&ash[3];
                asl[3] = pack_bf2(p12 - __bfloat162float(t->x), p13 - __bfloat162float(t->y));

                float c00 = sc[n0t][0], c01 = sc[n0t][1], c02 = sc[n0t][2], c03 = sc[n0t][3];
                float c10 = sc[n1t][0], c11 = sc[n1t][1], c12 = sc[n1t][2], c13 = sc[n1t][3];
                ach[0] = pack_bf2(c00, c01); ach[1] = pack_bf2(c02, c03);
                ach[2] = pack_bf2(c10, c11); ach[3] = pack_bf2(c12, c13);
                t = (__nv_bfloat162*)&ach[0];
                acl[0] = pack_bf2(c00 - __bfloat162float(t->x), c01 - __bfloat162float(t->y));
                t = (__nv_bfloat162*)&ach[1];
                acl[1] = pack_bf2(c02 - __bfloat162float(t->x), c03 - __bfloat162float(t->y));
                t = (__nv_bfloat162*)&ach[2];
                acl[2] = pack_bf2(c10 - __bfloat162float(t->x), c11 - __bfloat162float(t->y));
                t = (__nv_bfloat162*)&ach[3];
                acl[3] = pack_bf2(c12 - __bfloat162float(t->x), c13 - __bfloat162float(t->y));
            }
            #pragma unroll
            for (int n = 0; n < 8; n++) {
                const uint32_t vo = (n*8 + gg)*TSTR + j*32 + tt*4;
                uint32_t vsh0 = ld32s(kb + 4*AQ_B2 + vo), vsh1 = ld32s(kb + 4*AQ_B2 + vo + 16);
                uint32_t vsl0 = ld32s(kb + 5*AQ_B2 + vo), vsl1 = ld32s(kb + 5*AQ_B2 + vo + 16);
                uint32_t vch0 = ld32s(kb + 6*AQ_B2 + vo), vch1 = ld32s(kb + 6*AQ_B2 + vo + 16);
                uint32_t vcl0 = ld32s(kb + 7*AQ_B2 + vo), vcl1 = ld32s(kb + 7*AQ_B2 + vo + 16);
                mma16816(o[n], ash, vsh0, vsh1);
                mma16816(o[n], ash, vsl0, vsl1);
                mma16816(o[n], asl, vsh0, vsh1);
                mma16816(o[n], ach, vch0, vch1);
                mma16816(o[n], ach, vcl0, vcl1);
                mma16816(o[n], acl, vch0, vch1);
            }
        }
        __syncthreads();                       // KV slot reusable
        if (kt + 1 < 8) load_kv(kt + 1);       // overlaps co-resident CTA's compute
    }

    float li0 = (l0 > 0.f) ? (1.f / l0) : 0.f;
    float li1 = (l1 > 0.f) ? (1.f / l1) : 0.f;
    const size_t rA = (size_t)(b*512 + q0 + wq + gg) * DM + h*64;
    const size_t rB = rA + (size_t)8 * DM;
    #pragma unroll
    for (int n = 0; n < 8; n++) {
        int colg = n*8 + 2*tt;
        float v0 = o[n][0]*li0, v1 = o[n][1]*li0, v2 = o[n][2]*li1, v3 = o[n][3]*li1;
        uint32_t h0 = pack_bf2(v0, v1), h1 = pack_bf2(v2, v3);
        __nv_bfloat162* t0 = (__nv_bfloat162*)&h0;
        __nv_bfloat162* t1 = (__nv_bfloat162*)&h1;
        uint32_t lo0 = pack_bf2(v0 - __bfloat162float(t0->x), v1 - __bfloat162float(t0->y));
        uint32_t lo1 = pack_bf2(v2 - __bfloat162float(t1->x), v3 - __bfloat162float(t1->y));
        *(uint32_t*)(g_ath + rA + colg) = h0;
        *(uint32_t*)(g_atl + rA + colg) = lo0;
        *(uint32_t*)(g_ath + rB + colg) = h1;
        *(uint32_t*)(g_atl + rB + colg) = lo1;
    }
}

// ---------------- launch ----------------
extern "C" void kernel_launch(void* const* d_in, const int* in_sizes, int n_in,
                              void* d_out, int out_size)
{
    const float *x, *Wqs, *Wks, *Wvs, *Wqc, *Wkc, *Wvc, *Wo;
    const int *chain, *amask;

    if (in_sizes[0] == MROWS * DM) {
        x     = (const float*)d_in[0];
        chain = (const int*)d_in[1];
        amask = (const int*)d_in[2];
        Wqs = (const float*)d_in[3]; Wks = (const float*)d_in[4]; Wvs = (const float*)d_in[5];
        Wqc = (const float*)d_in[6]; Wkc = (const float*)d_in[7]; Wvc = (const float*)d_in[8];
        Wo  = (const float*)d_in[9];
    } else {
        Wkc = (const float*)d_in[0]; Wks = (const float*)d_in[1]; Wo  = (const float*)d_in[2];
        Wqc = (const float*)d_in[3]; Wqs = (const float*)d_in[4];
        Wvc = (const float*)d_in[5]; Wvs = (const float*)d_in[6];
        amask = (const int*)d_in[7]; chain = (const int*)d_in[8];
        x     = (const float*)d_in[9];
    }

    float *qs, *ks, *vs, *qc, *kc, *vc;
    cudaGetSymbolAddress((void**)&qs, g_qs);
    cudaGetSymbolAddress((void**)&ks, g_ks);
    cudaGetSymbolAddress((void**)&vs, g_vs);
    cudaGetSymbolAddress((void**)&qc, g_qc);
    cudaGetSymbolAddress((void**)&kc, g_kc);
    cudaGetSymbolAddress((void**)&vc, g_vc);
    __nv_bfloat16 *xh, *xl, *wth, *wtl, *ath, *atl;
    cudaGetSymbolAddress((void**)&xh,  g_xh);
    cudaGetSymbolAddress((void**)&xl,  g_xl);
    cudaGetSymbolAddress((void**)&wth, g_wth);
    cudaGetSymbolAddress((void**)&wtl, g_wtl);
    cudaGetSymbolAddress((void**)&ath, g_ath);
    cudaGetSymbolAddress((void**)&atl, g_atl);

    AttnP ap;
    {
        void* p;
        cudaGetSymbolAddress(&p, g_qsh);  ap.q0 = (const __nv_bfloat16*)p;
        cudaGetSymbolAddress(&p, g_qsl);  ap.q1 = (const __nv_bfloat16*)p;
        cudaGetSymbolAddress(&p, g_qch);  ap.q2 = (const __nv_bfloat16*)p;
        cudaGetSymbolAddress(&p, g_qcl);  ap.q3 = (const __nv_bfloat16*)p;
        cudaGetSymbolAddress(&p, g_ksh);  ap.k0 = (const __nv_bfloat16*)p;
        cudaGetSymbolAddress(&p, g_ksl);  ap.k1 = (const __nv_bfloat16*)p;
        cudaGetSymbolAddress(&p, g_kch);  ap.k2 = (const __nv_bfloat16*)p;
        cudaGetSymbolAddress(&p, g_kcl);  ap.k3 = (const __nv_bfloat16*)p;
        cudaGetSymbolAddress(&p, g_vsth); ap.v0 = (const __nv_bfloat16*)p;
        cudaGetSymbolAddress(&p, g_vstl); ap.v1 = (const __nv_bfloat16*)p;
        cudaGetSymbolAddress(&p, g_vcth); ap.v2 = (const __nv_bfloat16*)p;
        cudaGetSymbolAddress(&p, g_vctl); ap.v3 = (const __nv_bfloat16*)p;
    }
    ap.chain = chain; ap.amask = amask;

    // 1) merged prep
    W7 ws; ws.w[0]=Wqs; ws.w[1]=Wks; ws.w[2]=Wvs; ws.w[3]=Wqc; ws.w[4]=Wkc; ws.w[5]=Wvc; ws.w[6]=Wo;
    prep_all<<<4096 + 7168 + 64, 256>>>(x, ws);

    // 2) six projections on tensor cores (exact R5)
    cudaFuncSetAttribute(mma_gemm, cudaFuncAttributeMaxDynamicSharedMemorySize, GEMM_SMEM);
    TCGemm gp;
    gp.Ah = xh; gp.Al = xl; gp.Bh = wth; gp.Bl = wtl;
    gp.C[0]=qs; gp.C[1]=ks; gp.C[2]=vs; gp.C[3]=qc; gp.C[4]=kc; gp.C[5]=vc;
    mma_gemm<<<dim3(8, 32, 6), 256, GEMM_SMEM>>>(gp);

    // 3) merged rope/split + V transpose/split
    qv_prep<<<8192 + 8192, 256>>>();

    // 4) attention v2 (64-row CTAs, 2 CTAs/SM)
    cudaFuncSetAttribute(attn_mma, cudaFuncAttributeMaxDynamicSharedMemorySize, AT_SMEM2);
    attn_mma<<<dim3(8, 16, 8), 128, AT_SMEM2>>>(ap);

    // 5) output projection
    TCGemm go;
    go.Ah = ath; go.Al = atl; go.Bh = wth + (size_t)6*DM*DM; go.Bl = wtl + (size_t)6*DM*DM;
    go.C[0] = (float*)d_out;
    for (int i = 1; i < 6; i++) go.C[i] = (float*)d_out;
    mma_gemm<<<dim3(8, 32, 1), 256, GEMM_SMEM>>>(go);
}